// round 6
// baseline (speedup 1.0000x reference)
#include <cuda_runtime.h>
#include <math.h>

// ---- problem constants ----
#define NB_B   16
#define NB_S   512
#define NB_IN  256
#define NB_OUT 128
#define NB_NB  6
#define NB_SO  256
#define LN_EPS 1e-5f
#define TWO_PI 6.283185307179586f

typedef unsigned long long ull;

// ---- scratch ----
__device__ float g_Zt[NB_S * NB_OUT * NB_B];   // [s][j][b]
__device__ float g_R [NB_B * NB_S * NB_OUT];   // [b][s][i]
__device__ float g_T [NB_B * NB_S * NB_OUT];   // [b][s][i]
__device__ float g_Bt[NB_IN * 256];            // [k][n]  n<128: M, n>=128: res_W

__device__ __forceinline__ float cosa(float x) {
    float r; asm("cos.approx.f32 %0, %1;" : "=f"(r) : "f"(x)); return r;
}
__device__ __forceinline__ float rcpa(float x) {
    float r; asm("rcp.approx.f32 %0, %1;" : "=f"(r) : "f"(x)); return r;
}
#define FFMA2(d, a, b) asm("fma.rn.f32x2 %0, %1, %2, %0;" : "+l"(d) : "l"(a), "l"(b))
#define ADD2(d, a)     asm("add.rn.f32x2 %0, %0, %1;"     : "+l"(d) : "l"(a))
#define PACK2(d, f)    asm("mov.b64 %0, {%1, %1};" : "=l"(d) : "f"(f))

// ============================================================================
// K0: transpose [M; res_W] -> g_Bt[k][n]
// ============================================================================
__global__ __launch_bounds__(256) void k0_transpose(
    const float* __restrict__ M, const float* __restrict__ rW)
{
    __shared__ float t[32][33];
    const int k0 = blockIdx.x * 32;
    const int n0 = blockIdx.y * 32;
    const int lx = threadIdx.x & 31, ly = threadIdx.x >> 5;

    #pragma unroll
    for (int r = 0; r < 32; r += 8) {
        int n = n0 + ly + r;
        const float* src = (n < 128) ? (M + n * NB_IN) : (rW + (n - 128) * NB_IN);
        t[ly + r][lx] = src[k0 + lx];
    }
    __syncthreads();
    #pragma unroll
    for (int r = 0; r < 32; r += 8) {
        g_Bt[(k0 + ly + r) * 256 + n0 + lx] = t[lx][ly + r];
    }
}

// ============================================================================
// K1: Z = LN(x @ M^T) -> g_Zt[s][j][b],  R = x @ res_W^T -> g_R[b][s][i]
// ============================================================================
extern __shared__ float k1_sm[];
__global__ __launch_bounds__(512) void k1_proj_ln(
    const float* __restrict__ x, const float* __restrict__ lng,
    const float* __restrict__ lnb)
{
    float* As    = k1_sm;
    float* Bs    = k1_sm + 4096;
    float* zbuf  = k1_sm;
    float* rbuf  = k1_sm + 8192;
    float* musig = k1_sm + 20480;
    float* gb    = k1_sm + 20608;

    const int tid = threadIdx.x;
    const int s0  = blockIdx.x * 4;
    const int w   = tid >> 5;
    const int l   = tid & 31;
    const int h   = w >> 3;
    const int rg  = w & 7;
    const int cg  = l;

    ull accz[8][2], accr[8][2];
    #pragma unroll
    for (int r = 0; r < 8; r++) {
        accz[r][0] = 0ull; accz[r][1] = 0ull;
        accr[r][0] = 0ull; accr[r][1] = 0ull;
    }

    if (tid < 128) gb[tid] = lng[tid];
    else if (tid < 256) gb[tid] = lnb[tid - 128];

    float4 aR[2], bR[8];
    {
        #pragma unroll
        for (int t = 0; t < 2; t++) {
            int u = tid + t * 512;
            int hh = u >> 9, rem = u & 511, row = rem & 63, k4 = rem >> 6;
            int b = row >> 2, sl = row & 3;
            aR[t] = *(const float4*)(x + (b * NB_S + s0 + sl) * NB_IN + hh * 128 + k4 * 4);
        }
        const float4* src = (const float4*)g_Bt;
        #pragma unroll
        for (int t = 0; t < 8; t++) {
            int u = tid + t * 512;
            int hh = u >> 11, rem = u & 2047;
            bR[t] = src[(hh * 128) * 64 + rem];
        }
    }

    for (int it = 0; it < 4; it++) {
        #pragma unroll
        for (int t = 0; t < 2; t++) {
            int u = tid + t * 512;
            int hh = u >> 9, rem = u & 511, row = rem & 63, k4 = rem >> 6;
            float4 v = aR[t];
            As[hh * 2048 + (k4 * 4 + 0) * 64 + row] = v.x;
            As[hh * 2048 + (k4 * 4 + 1) * 64 + row] = v.y;
            As[hh * 2048 + (k4 * 4 + 2) * 64 + row] = v.z;
            As[hh * 2048 + (k4 * 4 + 3) * 64 + row] = v.w;
        }
        #pragma unroll
        for (int t = 0; t < 8; t++) {
            int u = tid + t * 512;
            ((float4*)Bs)[u] = bR[t];
        }
        __syncthreads();

        if (it < 3) {
            int kc = (it + 1) * 32;
            #pragma unroll
            for (int t = 0; t < 2; t++) {
                int u = tid + t * 512;
                int hh = u >> 9, rem = u & 511, row = rem & 63, k4 = rem >> 6;
                int b = row >> 2, sl = row & 3;
                aR[t] = *(const float4*)(x + (b * NB_S + s0 + sl) * NB_IN + hh * 128 + kc + k4 * 4);
            }
            const float4* src = (const float4*)g_Bt;
            #pragma unroll
            for (int t = 0; t < 8; t++) {
                int u = tid + t * 512;
                int hh = u >> 11, rem = u & 2047;
                bR[t] = src[(hh * 128 + kc) * 64 + rem];
            }
        }

        const float4* As4 = (const float4*)(As + h * 2048);
        const ulonglong2* B2 = (const ulonglong2*)(Bs + h * 8192);
        #pragma unroll 4
        for (int k = 0; k < 32; k++) {
            float4 a0 = As4[k * 16 + rg * 2];
            float4 a1 = As4[k * 16 + rg * 2 + 1];
            ulonglong2 bz = B2[k * 64 + cg];
            ulonglong2 br = B2[k * 64 + 32 + cg];
            ull pa[8];
            PACK2(pa[0], a0.x); PACK2(pa[1], a0.y); PACK2(pa[2], a0.z); PACK2(pa[3], a0.w);
            PACK2(pa[4], a1.x); PACK2(pa[5], a1.y); PACK2(pa[6], a1.z); PACK2(pa[7], a1.w);
            #pragma unroll
            for (int r = 0; r < 8; r++) {
                FFMA2(accz[r][0], pa[r], bz.x);
                FFMA2(accz[r][1], pa[r], bz.y);
                FFMA2(accr[r][0], pa[r], br.x);
                FFMA2(accr[r][1], pa[r], br.y);
            }
        }
        __syncthreads();
    }

    if (h == 0) {
        #pragma unroll
        for (int r = 0; r < 8; r++) {
            int row = rg * 8 + r;
            *(ull*)(zbuf + row * 128 + cg * 4)     = accz[r][0];
            *(ull*)(zbuf + row * 128 + cg * 4 + 2) = accz[r][1];
            *(ull*)(rbuf + row * 128 + cg * 4)     = accr[r][0];
            *(ull*)(rbuf + row * 128 + cg * 4 + 2) = accr[r][1];
        }
    }
    __syncthreads();
    if (h == 1) {
        #pragma unroll
        for (int r = 0; r < 8; r++) {
            int row = rg * 8 + r;
            ull* pz = (ull*)(zbuf + row * 128 + cg * 4);
            ull* pr = (ull*)(rbuf + row * 128 + cg * 4);
            ADD2(accz[r][0], pz[0]); ADD2(accz[r][1], pz[1]);
            ADD2(accr[r][0], pr[0]); ADD2(accr[r][1], pr[1]);
            pz[0] = accz[r][0]; pz[1] = accz[r][1];
            pr[0] = accr[r][0]; pr[1] = accr[r][1];
        }
    }
    __syncthreads();

    #pragma unroll
    for (int t = 0; t < 16; t++) {
        int u = tid + t * 512;
        int row = u >> 7, i = u & 127;
        int b = row >> 2, sl = row & 3;
        g_R[(b * NB_S + s0 + sl) * NB_OUT + i] = rbuf[row * 128 + i];
    }

    {
        int g = tid >> 3, l8 = tid & 7;
        float s1 = 0.f, s2 = 0.f;
        #pragma unroll
        for (int q = 0; q < 16; q++) {
            float v = zbuf[g * 128 + l8 * 16 + q];
            s1 += v; s2 = fmaf(v, v, s2);
        }
        #pragma unroll
        for (int m = 1; m < 8; m <<= 1) {
            s1 += __shfl_xor_sync(0xffffffffu, s1, m);
            s2 += __shfl_xor_sync(0xffffffffu, s2, m);
        }
        if (l8 == 0) {
            float mu  = s1 * (1.f / 128.f);
            float var = s2 * (1.f / 128.f) - mu * mu;
            musig[g * 2]     = mu;
            musig[g * 2 + 1] = rsqrtf(var + LN_EPS);
        }
    }
    __syncthreads();

    #pragma unroll
    for (int t = 0; t < 16; t++) {
        int idx = t * 512 + tid;
        int b = idx & 15, i = (idx >> 4) & 127, s = idx >> 11;
        int row = b * 4 + s;
        float v = zbuf[row * 128 + i];
        v = (v - musig[row * 2]) * musig[row * 2 + 1] * gb[i] + gb[128 + i];
        g_Zt[s0 * 2048 + idx] = v;
    }
}

// ============================================================================
// K2: W[s,i,j] = sum_g P[i,j,g]*cos(2*pi*s/p), p = i*768+j*6+g+2 (analytic)
//     T[b,s,i] = sum_j Z[b,s,j]*W[s,i,j]
// ============================================================================
extern __shared__ float k2_sm[];
__global__ __launch_bounds__(256) void k2_mix(const float* __restrict__ P)
{
    float* Ws = k2_sm;            // [4][128][32]
    float* Zs = k2_sm + 16384;    // [4][128][16]

    const int tid = threadIdx.x;
    const int s0  = blockIdx.x * 4;
    const int i0  = blockIdx.y * 32;

    {
        const float4* src = (const float4*)(g_Zt + s0 * 2048);
        float4* dst = (float4*)Zs;
        #pragma unroll
        for (int u = tid; u < 2048; u += 256) dst[u] = src[u];
    }

    {
        const int il = tid & 31;
        const int jb = tid >> 5;
        const int ig = i0 + il;
        #pragma unroll 1
        for (int jr = 0; jr < 16; jr++) {
            int j = jb + 8 * jr;
            int pb = (ig * 128 + j) * NB_NB;
            const float* Pp = P + pb;
            float pv[NB_NB], ip[NB_NB];
            #pragma unroll
            for (int g = 0; g < NB_NB; g++) {
                pv[g] = Pp[g];
                ip[g] = rcpa((float)(pb + g + 2));
            }
            #pragma unroll
            for (int sl = 0; sl < 4; sl++) {
                float sf = (float)(s0 + sl);
                float wv = 0.f;
                #pragma unroll
                for (int g = 0; g < NB_NB; g++) {
                    float t = sf * ip[g];
                    t -= floorf(t);
                    wv = fmaf(pv[g], cosa(TWO_PI * t), wv);
                }
                Ws[(sl * 128 + j) * 32 + il] = wv;
            }
        }
    }
    __syncthreads();

    {
        const int w  = tid >> 5;
        const int l  = tid & 31;
        const int s  = w >> 1;
        const int bh = w & 1;
        const int bq = l >> 3;
        const int iq = l & 7;
        const int b0 = bh * 8 + bq * 2;

        ull acc[2][2];
        acc[0][0] = 0ull; acc[0][1] = 0ull; acc[1][0] = 0ull; acc[1][1] = 0ull;

        const ull* Zp = (const ull*)Zs + s * 1024 + (b0 >> 1);
        const ulonglong2* Wp = (const ulonglong2*)Ws + s * 1024 + iq;
        #pragma unroll 8
        for (int j = 0; j < 128; j++) {
            ull zu = Zp[j * 8];
            float2 z = *(float2*)&zu;
            ulonglong2 wv = Wp[j * 8];
            ull pz;
            PACK2(pz, z.x); FFMA2(acc[0][0], pz, wv.x); FFMA2(acc[0][1], pz, wv.y);
            PACK2(pz, z.y); FFMA2(acc[1][0], pz, wv.x); FFMA2(acc[1][1], pz, wv.y);
        }
        int sg = s0 + s;
        #pragma unroll
        for (int bi = 0; bi < 2; bi++) {
            int b = b0 + bi;
            ulonglong2 o; o.x = acc[bi][0]; o.y = acc[bi][1];
            *(ulonglong2*)(g_T + (b * NB_S + sg) * NB_OUT + i0 + iq * 4) = o;
        }
    }
}

// ============================================================================
// K3: out[b,o,i] = sum_{k<2L} A[k,o]*Bm[b,k,i]
//     A[2s+t] = (t? res_linker : Linker)[s],  Bm[b,2s+t] = (t? g_R : g_T)[b,s]
// Block (o-tile 32, b). 512 threads = 4 o-groups x 4 k-quarters.
// Thread tile 8 o x 4 i (A is warp-uniform broadcast -> high FMA/LDS ratio).
// Chunked smem pipeline: 8 chunks of 128 k, LDG->reg->STS prefetch.
// ============================================================================
extern __shared__ float k3_sm[];
// As [128 k][32 o] @0 (4096 fl) | Bs [128 k][128 i] @4096 (16384 fl)  = 80KB
// reduction staging reuses Bs
__global__ __launch_bounds__(512) void k3_link(
    const float* __restrict__ Lk, const float* __restrict__ rLk,
    float* __restrict__ out, const int* __restrict__ pL)
{
    float* As = k3_sm;
    float* Bs = k3_sm + 4096;

    const int tid = threadIdx.x;
    const int o0 = blockIdx.x * 32;
    const int b  = blockIdx.y;
    const int L  = pL[0];
    const int Lo = (L / 2) > 1 ? (L / 2) : 1;
    const int L2 = L * 2;

    const int w  = tid >> 5;
    const int l  = tid & 31;
    const int og = w & 3;       // o-group: o = o0 + og*8 + oi
    const int q  = w >> 2;      // k-quarter 0..3 (k in [q*32, q*32+32) per chunk)

    ull acc[8][2];
    #pragma unroll
    for (int a = 0; a < 8; a++) { acc[a][0] = 0ull; acc[a][1] = 0ull; }

    float4 aR[2], bR[8];
    const float4 z4 = make_float4(0.f, 0.f, 0.f, 0.f);

    // prefetch chunk 0 (128 global k rows)
    {
        #pragma unroll
        for (int t = 0; t < 2; t++) {
            int u = tid + t * 512;          // 0..1023
            int k = u >> 3, oq = u & 7;
            int sg = k >> 1, tt = k & 1;
            aR[t] = (k < L2) ? *(const float4*)((tt ? rLk : Lk) + sg * NB_SO + o0 + oq * 4) : z4;
        }
        #pragma unroll
        for (int t = 0; t < 8; t++) {
            int u = tid + t * 512;          // 0..4095
            int k = u >> 5, iq = u & 31;
            int sg = k >> 1, tt = k & 1;
            bR[t] = (k < L2) ? *(const float4*)((tt ? g_R : g_T) + (b * NB_S + sg) * NB_OUT + iq * 4) : z4;
        }
    }

    for (int c = 0; c < 8; c++) {
        #pragma unroll
        for (int t = 0; t < 2; t++) ((float4*)As)[tid + t * 512] = aR[t];
        #pragma unroll
        for (int t = 0; t < 8; t++) ((float4*)Bs)[tid + t * 512] = bR[t];
        __syncthreads();

        if (c < 7) {
            int kc = (c + 1) * 128;
            #pragma unroll
            for (int t = 0; t < 2; t++) {
                int u = tid + t * 512;
                int k = u >> 3, oq = u & 7;
                int kg = kc + k;
                int sg = kg >> 1, tt = kg & 1;
                aR[t] = (kg < L2) ? *(const float4*)((tt ? rLk : Lk) + sg * NB_SO + o0 + oq * 4) : z4;
            }
            #pragma unroll
            for (int t = 0; t < 8; t++) {
                int u = tid + t * 512;
                int k = u >> 5, iq = u & 31;
                int kg = kc + k;
                int sg = kg >> 1, tt = kg & 1;
                bR[t] = (kg < L2) ? *(const float4*)((tt ? g_R : g_T) + (b * NB_S + sg) * NB_OUT + iq * 4) : z4;
            }
        }

        // compute: quarter q handles k rows [q*32, q*32+32)
        const float4* Af = (const float4*)As + (q * 32) * 8 + og * 2;
        const ulonglong2* B2 = (const ulonglong2*)Bs + (q * 32) * 32 + l;
        #pragma unroll 4
        for (int k = 0; k < 32; k++) {
            float4 a0 = Af[k * 8];          // broadcast (warp-uniform)
            float4 a1 = Af[k * 8 + 1];      // broadcast
            ulonglong2 bv = B2[k * 32];
            ull pa[8];
            PACK2(pa[0], a0.x); PACK2(pa[1], a0.y); PACK2(pa[2], a0.z); PACK2(pa[3], a0.w);
            PACK2(pa[4], a1.x); PACK2(pa[5], a1.y); PACK2(pa[6], a1.z); PACK2(pa[7], a1.w);
            #pragma unroll
            for (int oi = 0; oi < 8; oi++) {
                FFMA2(acc[oi][0], pa[oi], bv.x);
                FFMA2(acc[oi][1], pa[oi], bv.y);
            }
        }
        __syncthreads();
    }

    // 4-way split-K reduction through Bs (12288 fl used <= 16384)
    if (q > 0) {
        ulonglong2* st = (ulonglong2*)Bs + ((q - 1) * 4 + og) * 256;
        #pragma unroll
        for (int oi = 0; oi < 8; oi++) {
            ulonglong2 v; v.x = acc[oi][0]; v.y = acc[oi][1];
            st[oi * 32 + l] = v;
        }
    }
    __syncthreads();
    if (q == 0) {
        #pragma unroll
        for (int oi = 0; oi < 8; oi++) {
            #pragma unroll
            for (int qq = 0; qq < 3; qq++) {
                ulonglong2 v = ((const ulonglong2*)Bs)[(qq * 4 + og) * 256 + oi * 32 + l];
                ADD2(acc[oi][0], v.x);
                ADD2(acc[oi][1], v.y);
            }
            int o = o0 + og * 8 + oi;
            if (o < Lo) {
                ulonglong2 ov; ov.x = acc[oi][0]; ov.y = acc[oi][1];
                *(ulonglong2*)(out + (b * Lo + o) * NB_OUT + l * 4) = ov;
            }
        }
    }
}

// ============================================================================
extern "C" void kernel_launch(void* const* d_in, const int* in_sizes, int n_in,
                              void* d_out, int out_size)
{
    const float* x    = (const float*)d_in[0];
    const float* M    = (const float*)d_in[1];
    const float* P    = (const float*)d_in[2];
    const float* Lk   = (const float*)d_in[3];
    const float* lng  = (const float*)d_in[4];
    const float* lnb  = (const float*)d_in[5];
    const float* rW   = (const float*)d_in[6];
    const float* rLk  = (const float*)d_in[7];
    const int*   pL   = (const int*)d_in[9];
    float* out = (float*)d_out;

    cudaFuncSetAttribute(k1_proj_ln, cudaFuncAttributeMaxDynamicSharedMemorySize, 84992);
    cudaFuncSetAttribute(k2_mix,     cudaFuncAttributeMaxDynamicSharedMemorySize, 98304);
    cudaFuncSetAttribute(k3_link,    cudaFuncAttributeMaxDynamicSharedMemorySize, 81920);

    k0_transpose<<<dim3(8, 8), 256>>>(M, rW);
    k1_proj_ln<<<NB_S / 4, 512, 84992>>>(x, lng, lnb);
    k2_mix<<<dim3(NB_S / 4, NB_OUT / 32), 256, 98304>>>(P);
    k3_link<<<dim3(8, NB_B), 512, 81920>>>(Lk, rLk, out, pL);
}

// round 8
// speedup vs baseline: 1.5537x; 1.5537x over previous
#include <cuda_runtime.h>
#include <math.h>

// ---- problem constants ----
#define NB_B   16
#define NB_S   512
#define NB_IN  256
#define NB_OUT 128
#define NB_NB  6
#define NB_SO  256
#define LN_EPS 1e-5f
#define TWO_PI 6.283185307179586f

typedef unsigned long long ull;

// ---- scratch ----
__device__ float g_Zt[NB_S * NB_OUT * NB_B];   // [s][j][b]
__device__ float g_R [NB_B * NB_S * NB_OUT];   // [b][s][i]
__device__ float g_T [NB_B * NB_S * NB_OUT];   // [b][s][i]
__device__ float g_Bt[NB_IN * 256];            // [k][n]  n<128: M, n>=128: res_W

__device__ __forceinline__ float cosa(float x) {
    float r; asm("cos.approx.f32 %0, %1;" : "=f"(r) : "f"(x)); return r;
}
__device__ __forceinline__ float rcpa(float x) {
    float r; asm("rcp.approx.f32 %0, %1;" : "=f"(r) : "f"(x)); return r;
}
#define FFMA2(d, a, b) asm("fma.rn.f32x2 %0, %1, %2, %0;" : "+l"(d) : "l"(a), "l"(b))
#define ADD2(d, a)     asm("add.rn.f32x2 %0, %0, %1;"     : "+l"(d) : "l"(a))
#define PACK2(d, f)    asm("mov.b64 %0, {%1, %1};" : "=l"(d) : "f"(f))

// ============================================================================
// K0: transpose [M; res_W] -> g_Bt[k][n]
// ============================================================================
__global__ __launch_bounds__(256) void k0_transpose(
    const float* __restrict__ M, const float* __restrict__ rW)
{
    __shared__ float t[32][33];
    const int k0 = blockIdx.x * 32;
    const int n0 = blockIdx.y * 32;
    const int lx = threadIdx.x & 31, ly = threadIdx.x >> 5;

    #pragma unroll
    for (int r = 0; r < 32; r += 8) {
        int n = n0 + ly + r;
        const float* src = (n < 128) ? (M + n * NB_IN) : (rW + (n - 128) * NB_IN);
        t[ly + r][lx] = src[k0 + lx];
    }
    __syncthreads();
    #pragma unroll
    for (int r = 0; r < 32; r += 8) {
        g_Bt[(k0 + ly + r) * 256 + n0 + lx] = t[lx][ly + r];
    }
}

// ============================================================================
// K1: Z = LN(x @ M^T) -> g_Zt[s][j][b],  R = x @ res_W^T -> g_R[b][s][i]
// ============================================================================
extern __shared__ float k1_sm[];
__global__ __launch_bounds__(512) void k1_proj_ln(
    const float* __restrict__ x, const float* __restrict__ lng,
    const float* __restrict__ lnb)
{
    float* As    = k1_sm;
    float* Bs    = k1_sm + 4096;
    float* zbuf  = k1_sm;
    float* rbuf  = k1_sm + 8192;
    float* musig = k1_sm + 20480;
    float* gb    = k1_sm + 20608;

    const int tid = threadIdx.x;
    const int s0  = blockIdx.x * 4;
    const int w   = tid >> 5;
    const int l   = tid & 31;
    const int h   = w >> 3;
    const int rg  = w & 7;
    const int cg  = l;

    ull accz[8][2], accr[8][2];
    #pragma unroll
    for (int r = 0; r < 8; r++) {
        accz[r][0] = 0ull; accz[r][1] = 0ull;
        accr[r][0] = 0ull; accr[r][1] = 0ull;
    }

    if (tid < 128) gb[tid] = lng[tid];
    else if (tid < 256) gb[tid] = lnb[tid - 128];

    float4 aR[2], bR[8];
    {
        #pragma unroll
        for (int t = 0; t < 2; t++) {
            int u = tid + t * 512;
            int hh = u >> 9, rem = u & 511, row = rem & 63, k4 = rem >> 6;
            int b = row >> 2, sl = row & 3;
            aR[t] = *(const float4*)(x + (b * NB_S + s0 + sl) * NB_IN + hh * 128 + k4 * 4);
        }
        const float4* src = (const float4*)g_Bt;
        #pragma unroll
        for (int t = 0; t < 8; t++) {
            int u = tid + t * 512;
            int hh = u >> 11, rem = u & 2047;
            bR[t] = src[(hh * 128) * 64 + rem];
        }
    }

    for (int it = 0; it < 4; it++) {
        #pragma unroll
        for (int t = 0; t < 2; t++) {
            int u = tid + t * 512;
            int hh = u >> 9, rem = u & 511, row = rem & 63, k4 = rem >> 6;
            float4 v = aR[t];
            As[hh * 2048 + (k4 * 4 + 0) * 64 + row] = v.x;
            As[hh * 2048 + (k4 * 4 + 1) * 64 + row] = v.y;
            As[hh * 2048 + (k4 * 4 + 2) * 64 + row] = v.z;
            As[hh * 2048 + (k4 * 4 + 3) * 64 + row] = v.w;
        }
        #pragma unroll
        for (int t = 0; t < 8; t++) {
            int u = tid + t * 512;
            ((float4*)Bs)[u] = bR[t];
        }
        __syncthreads();

        if (it < 3) {
            int kc = (it + 1) * 32;
            #pragma unroll
            for (int t = 0; t < 2; t++) {
                int u = tid + t * 512;
                int hh = u >> 9, rem = u & 511, row = rem & 63, k4 = rem >> 6;
                int b = row >> 2, sl = row & 3;
                aR[t] = *(const float4*)(x + (b * NB_S + s0 + sl) * NB_IN + hh * 128 + kc + k4 * 4);
            }
            const float4* src = (const float4*)g_Bt;
            #pragma unroll
            for (int t = 0; t < 8; t++) {
                int u = tid + t * 512;
                int hh = u >> 11, rem = u & 2047;
                bR[t] = src[(hh * 128 + kc) * 64 + rem];
            }
        }

        const float4* As4 = (const float4*)(As + h * 2048);
        const ulonglong2* B2 = (const ulonglong2*)(Bs + h * 8192);
        #pragma unroll 4
        for (int k = 0; k < 32; k++) {
            float4 a0 = As4[k * 16 + rg * 2];
            float4 a1 = As4[k * 16 + rg * 2 + 1];
            ulonglong2 bz = B2[k * 64 + cg];
            ulonglong2 br = B2[k * 64 + 32 + cg];
            ull pa[8];
            PACK2(pa[0], a0.x); PACK2(pa[1], a0.y); PACK2(pa[2], a0.z); PACK2(pa[3], a0.w);
            PACK2(pa[4], a1.x); PACK2(pa[5], a1.y); PACK2(pa[6], a1.z); PACK2(pa[7], a1.w);
            #pragma unroll
            for (int r = 0; r < 8; r++) {
                FFMA2(accz[r][0], pa[r], bz.x);
                FFMA2(accz[r][1], pa[r], bz.y);
                FFMA2(accr[r][0], pa[r], br.x);
                FFMA2(accr[r][1], pa[r], br.y);
            }
        }
        __syncthreads();
    }

    if (h == 0) {
        #pragma unroll
        for (int r = 0; r < 8; r++) {
            int row = rg * 8 + r;
            *(ull*)(zbuf + row * 128 + cg * 4)     = accz[r][0];
            *(ull*)(zbuf + row * 128 + cg * 4 + 2) = accz[r][1];
            *(ull*)(rbuf + row * 128 + cg * 4)     = accr[r][0];
            *(ull*)(rbuf + row * 128 + cg * 4 + 2) = accr[r][1];
        }
    }
    __syncthreads();
    if (h == 1) {
        #pragma unroll
        for (int r = 0; r < 8; r++) {
            int row = rg * 8 + r;
            ull* pz = (ull*)(zbuf + row * 128 + cg * 4);
            ull* pr = (ull*)(rbuf + row * 128 + cg * 4);
            ADD2(accz[r][0], pz[0]); ADD2(accz[r][1], pz[1]);
            ADD2(accr[r][0], pr[0]); ADD2(accr[r][1], pr[1]);
            pz[0] = accz[r][0]; pz[1] = accz[r][1];
            pr[0] = accr[r][0]; pr[1] = accr[r][1];
        }
    }
    __syncthreads();

    #pragma unroll
    for (int t = 0; t < 16; t++) {
        int u = tid + t * 512;
        int row = u >> 7, i = u & 127;
        int b = row >> 2, sl = row & 3;
        g_R[(b * NB_S + s0 + sl) * NB_OUT + i] = rbuf[row * 128 + i];
    }

    {
        int g = tid >> 3, l8 = tid & 7;
        float s1 = 0.f, s2 = 0.f;
        #pragma unroll
        for (int q = 0; q < 16; q++) {
            float v = zbuf[g * 128 + l8 * 16 + q];
            s1 += v; s2 = fmaf(v, v, s2);
        }
        #pragma unroll
        for (int m = 1; m < 8; m <<= 1) {
            s1 += __shfl_xor_sync(0xffffffffu, s1, m);
            s2 += __shfl_xor_sync(0xffffffffu, s2, m);
        }
        if (l8 == 0) {
            float mu  = s1 * (1.f / 128.f);
            float var = s2 * (1.f / 128.f) - mu * mu;
            musig[g * 2]     = mu;
            musig[g * 2 + 1] = rsqrtf(var + LN_EPS);
        }
    }
    __syncthreads();

    #pragma unroll
    for (int t = 0; t < 16; t++) {
        int idx = t * 512 + tid;
        int b = idx & 15, i = (idx >> 4) & 127, s = idx >> 11;
        int row = b * 4 + s;
        float v = zbuf[row * 128 + i];
        v = (v - musig[row * 2]) * musig[row * 2 + 1] * gb[i] + gb[128 + i];
        g_Zt[s0 * 2048 + idx] = v;
    }
}

// ============================================================================
// K2: W[s,i,j] = sum_g P[i,j,g]*cos(2*pi*s/p), p = i*768+j*6+g+2 (analytic)
//     T[b,s,i] = sum_j Z[b,s,j]*W[s,i,j]
// frac range-reduction only needed when p can be <= s_max (i.e. i-block 0);
// for i >= 32, p >= 24578 so |arg| < 2*pi*511/24578 << 1 rad.
// ============================================================================
extern __shared__ float k2_sm[];
__global__ __launch_bounds__(256) void k2_mix(const float* __restrict__ P)
{
    float* Ws = k2_sm;            // [4][128][32]
    float* Zs = k2_sm + 16384;    // [4][128][16]

    const int tid = threadIdx.x;
    const int s0  = blockIdx.x * 4;
    const int i0  = blockIdx.y * 32;

    {
        const float4* src = (const float4*)(g_Zt + s0 * 2048);
        float4* dst = (float4*)Zs;
        #pragma unroll
        for (int u = tid; u < 2048; u += 256) dst[u] = src[u];
    }

    {
        const int il = tid & 31;
        const int jb = tid >> 5;
        const int ig = i0 + il;
        if (i0 == 0) {
            // p can be small: full frac range reduction
            #pragma unroll 1
            for (int jr = 0; jr < 16; jr++) {
                int j = jb + 8 * jr;
                int pb = (ig * 128 + j) * NB_NB;
                const float* Pp = P + pb;
                float pv[NB_NB], ip[NB_NB];
                #pragma unroll
                for (int g = 0; g < NB_NB; g++) {
                    pv[g] = Pp[g];
                    ip[g] = rcpa((float)(pb + g + 2));
                }
                #pragma unroll
                for (int sl = 0; sl < 4; sl++) {
                    float sf = (float)(s0 + sl);
                    float wv = 0.f;
                    #pragma unroll
                    for (int g = 0; g < NB_NB; g++) {
                        float t = sf * ip[g];
                        t -= floorf(t);
                        wv = fmaf(pv[g], cosa(TWO_PI * t), wv);
                    }
                    Ws[(sl * 128 + j) * 32 + il] = wv;
                }
            }
        } else {
            // p >= 24578 > s_max: argument < 0.14 rad, no reduction needed
            #pragma unroll 1
            for (int jr = 0; jr < 16; jr++) {
                int j = jb + 8 * jr;
                int pb = (ig * 128 + j) * NB_NB;
                const float* Pp = P + pb;
                float pv[NB_NB], ip[NB_NB];
                #pragma unroll
                for (int g = 0; g < NB_NB; g++) {
                    pv[g] = Pp[g];
                    ip[g] = rcpa((float)(pb + g + 2)) * TWO_PI;
                }
                #pragma unroll
                for (int sl = 0; sl < 4; sl++) {
                    float sf = (float)(s0 + sl);
                    float wv = 0.f;
                    #pragma unroll
                    for (int g = 0; g < NB_NB; g++) {
                        wv = fmaf(pv[g], cosa(sf * ip[g]), wv);
                    }
                    Ws[(sl * 128 + j) * 32 + il] = wv;
                }
            }
        }
    }
    __syncthreads();

    {
        const int w  = tid >> 5;
        const int l  = tid & 31;
        const int s  = w >> 1;
        const int bh = w & 1;
        const int bq = l >> 3;
        const int iq = l & 7;
        const int b0 = bh * 8 + bq * 2;

        ull acc[2][2];
        acc[0][0] = 0ull; acc[0][1] = 0ull; acc[1][0] = 0ull; acc[1][1] = 0ull;

        const ull* Zp = (const ull*)Zs + s * 1024 + (b0 >> 1);
        const ulonglong2* Wp = (const ulonglong2*)Ws + s * 1024 + iq;
        #pragma unroll 8
        for (int j = 0; j < 128; j++) {
            ull zu = Zp[j * 8];
            float2 z = *(float2*)&zu;
            ulonglong2 wv = Wp[j * 8];
            ull pz;
            PACK2(pz, z.x); FFMA2(acc[0][0], pz, wv.x); FFMA2(acc[0][1], pz, wv.y);
            PACK2(pz, z.y); FFMA2(acc[1][0], pz, wv.x); FFMA2(acc[1][1], pz, wv.y);
        }
        int sg = s0 + s;
        #pragma unroll
        for (int bi = 0; bi < 2; bi++) {
            int b = b0 + bi;
            ulonglong2 o; o.x = acc[bi][0]; o.y = acc[bi][1];
            *(ulonglong2*)(g_T + (b * NB_S + sg) * NB_OUT + i0 + iq * 4) = o;
        }
    }
}

// ============================================================================
// K3 (R4 configuration): out[b,o,i] = sum_{k<2L} A[k,o]*Bm[b,k,i]
//     A[2s+t] = (t? res_linker : Linker)[s],  Bm[b,2s+t] = (t? g_R : g_T)[b,s]
// Block (o-tile 32, b). 512 threads, split-K halves, warp covers 4 o x 128 i,
// thread 4 o x 4 i. LDG->reg->STS pipeline over 8 chunks of 64 k.
// ============================================================================
extern __shared__ float k3_sm[];
// As2[2][64][32] @0 (4096) | Bs2[2][64][128] @4096 (16384)  total 80KB
__global__ __launch_bounds__(512) void k3_link(
    const float* __restrict__ Lk, const float* __restrict__ rLk,
    float* __restrict__ out, const int* __restrict__ pL)
{
    float* As = k3_sm;
    float* Bs = k3_sm + 4096;

    const int tid = threadIdx.x;
    const int o0 = blockIdx.x * 32;
    const int b  = blockIdx.y;
    const int L  = pL[0];
    const int Lo = (L / 2) > 1 ? (L / 2) : 1;
    const int L2 = L * 2;

    const int w  = tid >> 5;
    const int l  = tid & 31;
    const int h  = w >> 3;
    const int wo = w & 7;

    ull acc[4][2];
    #pragma unroll
    for (int a = 0; a < 4; a++) { acc[a][0] = 0ull; acc[a][1] = 0ull; }

    float4 aR[2], bR[8];
    const float4 z4 = make_float4(0.f, 0.f, 0.f, 0.f);

    // prefetch chunk 0
    {
        #pragma unroll
        for (int t = 0; t < 2; t++) {
            int u = tid + t * 512;
            int hh = u >> 9, rem = u & 511, k = rem >> 3, q = rem & 7;
            int kg = hh * 512 + k;
            int sg = kg >> 1, tt = kg & 1;
            aR[t] = (kg < L2) ? *(const float4*)((tt ? rLk : Lk) + sg * NB_SO + o0 + q * 4) : z4;
        }
        #pragma unroll
        for (int t = 0; t < 8; t++) {
            int u = tid + t * 512;
            int hh = u >> 11, rem = u & 2047, k = rem >> 5, q = rem & 31;
            int kg = hh * 512 + k;
            int sg = kg >> 1, tt = kg & 1;
            bR[t] = (kg < L2) ? *(const float4*)((tt ? g_R : g_T) + (b * NB_S + sg) * NB_OUT + q * 4) : z4;
        }
    }

    for (int c = 0; c < 8; c++) {
        #pragma unroll
        for (int t = 0; t < 2; t++) {
            int u = tid + t * 512;
            ((float4*)As)[u] = aR[t];
        }
        #pragma unroll
        for (int t = 0; t < 8; t++) {
            int u = tid + t * 512;
            ((float4*)Bs)[u] = bR[t];
        }
        __syncthreads();

        if (c < 7) {
            int kc = (c + 1) * 64;
            #pragma unroll
            for (int t = 0; t < 2; t++) {
                int u = tid + t * 512;
                int hh = u >> 9, rem = u & 511, k = rem >> 3, q = rem & 7;
                int kg = hh * 512 + kc + k;
                int sg = kg >> 1, tt = kg & 1;
                aR[t] = (kg < L2) ? *(const float4*)((tt ? rLk : Lk) + sg * NB_SO + o0 + q * 4) : z4;
            }
            #pragma unroll
            for (int t = 0; t < 8; t++) {
                int u = tid + t * 512;
                int hh = u >> 11, rem = u & 2047, k = rem >> 5, q = rem & 31;
                int kg = hh * 512 + kc + k;
                int sg = kg >> 1, tt = kg & 1;
                bR[t] = (kg < L2) ? *(const float4*)((tt ? g_R : g_T) + (b * NB_S + sg) * NB_OUT + q * 4) : z4;
            }
        }

        const float4* Af = (const float4*)As + h * 512 + wo;
        const ulonglong2* B2 = (const ulonglong2*)Bs + h * 2048 + l;
        #pragma unroll 4
        for (int k = 0; k < 64; k++) {
            float4 a = Af[k * 8];
            ulonglong2 bv = B2[k * 32];
            ull pa[4];
            PACK2(pa[0], a.x); PACK2(pa[1], a.y); PACK2(pa[2], a.z); PACK2(pa[3], a.w);
            #pragma unroll
            for (int oi = 0; oi < 4; oi++) {
                FFMA2(acc[oi][0], pa[oi], bv.x);
                FFMA2(acc[oi][1], pa[oi], bv.y);
            }
        }
        __syncthreads();
    }

    // cross-half reduction via As region
    if (h == 1) {
        #pragma unroll
        for (int oi = 0; oi < 4; oi++) {
            ulonglong2 v; v.x = acc[oi][0]; v.y = acc[oi][1];
            ((ulonglong2*)As)[(oi * 8 + wo) * 32 + l] = v;
        }
    }
    __syncthreads();
    if (h == 0) {
        #pragma unroll
        for (int oi = 0; oi < 4; oi++) {
            ulonglong2 v = ((ulonglong2*)As)[(oi * 8 + wo) * 32 + l];
            ADD2(acc[oi][0], v.x);
            ADD2(acc[oi][1], v.y);
            int o = o0 + wo * 4 + oi;
            if (o < Lo) {
                ulonglong2 ov; ov.x = acc[oi][0]; ov.y = acc[oi][1];
                *(ulonglong2*)(out + (b * Lo + o) * NB_OUT + l * 4) = ov;
            }
        }
    }
}

// ============================================================================
extern "C" void kernel_launch(void* const* d_in, const int* in_sizes, int n_in,
                              void* d_out, int out_size)
{
    const float* x    = (const float*)d_in[0];
    const float* M    = (const float*)d_in[1];
    const float* P    = (const float*)d_in[2];
    const float* Lk   = (const float*)d_in[3];
    const float* lng  = (const float*)d_in[4];
    const float* lnb  = (const float*)d_in[5];
    const float* rW   = (const float*)d_in[6];
    const float* rLk  = (const float*)d_in[7];
    const int*   pL   = (const int*)d_in[9];
    float* out = (float*)d_out;

    cudaFuncSetAttribute(k1_proj_ln, cudaFuncAttributeMaxDynamicSharedMemorySize, 84992);
    cudaFuncSetAttribute(k2_mix,     cudaFuncAttributeMaxDynamicSharedMemorySize, 98304);
    cudaFuncSetAttribute(k3_link,    cudaFuncAttributeMaxDynamicSharedMemorySize, 81920);

    k0_transpose<<<dim3(8, 8), 256>>>(M, rW);
    k1_proj_ln<<<NB_S / 4, 512, 84992>>>(x, lng, lnb);
    k2_mix<<<dim3(NB_S / 4, NB_OUT / 32), 256, 98304>>>(P);
    k3_link<<<dim3(8, NB_B), 512, 81920>>>(Lk, rLk, out, pL);
}

// round 12
// speedup vs baseline: 1.6635x; 1.0707x over previous
#include <cuda_runtime.h>
#include <cstdint>
#include <math.h>

// ---- problem constants ----
#define NB_B   16
#define NB_S   512
#define NB_IN  256
#define NB_OUT 128
#define NB_NB  6
#define NB_SO  256
#define LN_EPS 1e-5f
#define TWO_PI 6.283185307179586f

typedef unsigned long long ull;

// ---- scratch ----
__device__ float g_Zt[NB_S * NB_OUT * NB_B];   // [s][j][b]
__device__ float g_R [NB_B * NB_S * NB_OUT];   // [b][s][i]
__device__ float g_T [NB_B * NB_S * NB_OUT];   // [b][s][i]
__device__ float g_Bt[NB_IN * 256];            // [k][n]  n<128: M, n>=128: res_W

__device__ __forceinline__ float cosa(float x) {
    float r; asm("cos.approx.f32 %0, %1;" : "=f"(r) : "f"(x)); return r;
}
__device__ __forceinline__ float rcpa(float x) {
    float r; asm("rcp.approx.f32 %0, %1;" : "=f"(r) : "f"(x)); return r;
}
#define FFMA2(d, a, b) asm("fma.rn.f32x2 %0, %1, %2, %0;" : "+l"(d) : "l"(a), "l"(b))
#define ADD2(d, a)     asm("add.rn.f32x2 %0, %0, %1;"     : "+l"(d) : "l"(a))
#define PACK2(d, f)    asm("mov.b64 %0, {%1, %1};" : "=l"(d) : "f"(f))

// cp.async 16B with zero-fill predicate (src-size 0 when pred false)
__device__ __forceinline__ void cp16(uint32_t dst, const void* src, bool pred) {
    int sz = pred ? 16 : 0;
    asm volatile("cp.async.cg.shared.global [%0], [%1], 16, %2;"
                 :: "r"(dst), "l"(src), "r"(sz));
}
#define CP_COMMIT() asm volatile("cp.async.commit_group;" ::: "memory")
#define CP_WAIT(n)  asm volatile("cp.async.wait_group %0;" :: "n"(n) : "memory")

// ============================================================================
// K0: transpose [M; res_W] -> g_Bt[k][n]
// ============================================================================
__global__ __launch_bounds__(256) void k0_transpose(
    const float* __restrict__ M, const float* __restrict__ rW)
{
    __shared__ float t[32][33];
    const int k0 = blockIdx.x * 32;
    const int n0 = blockIdx.y * 32;
    const int lx = threadIdx.x & 31, ly = threadIdx.x >> 5;

    #pragma unroll
    for (int r = 0; r < 32; r += 8) {
        int n = n0 + ly + r;
        const float* src = (n < 128) ? (M + n * NB_IN) : (rW + (n - 128) * NB_IN);
        t[ly + r][lx] = src[k0 + lx];
    }
    __syncthreads();
    #pragma unroll
    for (int r = 0; r < 32; r += 8) {
        g_Bt[(k0 + ly + r) * 256 + n0 + lx] = t[lx][ly + r];
    }
}

// ============================================================================
// K1: Z = LN(x @ M^T) -> g_Zt[s][j][b],  R = x @ res_W^T -> g_R[b][s][i]
// ============================================================================
extern __shared__ float k1_sm[];
__global__ __launch_bounds__(512) void k1_proj_ln(
    const float* __restrict__ x, const float* __restrict__ lng,
    const float* __restrict__ lnb)
{
    float* As    = k1_sm;
    float* Bs    = k1_sm + 4096;
    float* zbuf  = k1_sm;
    float* rbuf  = k1_sm + 8192;
    float* musig = k1_sm + 20480;
    float* gb    = k1_sm + 20608;

    const int tid = threadIdx.x;
    const int s0  = blockIdx.x * 4;
    const int w   = tid >> 5;
    const int l   = tid & 31;
    const int h   = w >> 3;
    const int rg  = w & 7;
    const int cg  = l;

    ull accz[8][2], accr[8][2];
    #pragma unroll
    for (int r = 0; r < 8; r++) {
        accz[r][0] = 0ull; accz[r][1] = 0ull;
        accr[r][0] = 0ull; accr[r][1] = 0ull;
    }

    if (tid < 128) gb[tid] = lng[tid];
    else if (tid < 256) gb[tid] = lnb[tid - 128];

    float4 aR[2], bR[8];
    {
        #pragma unroll
        for (int t = 0; t < 2; t++) {
            int u = tid + t * 512;
            int hh = u >> 9, rem = u & 511, row = rem & 63, k4 = rem >> 6;
            int b = row >> 2, sl = row & 3;
            aR[t] = *(const float4*)(x + (b * NB_S + s0 + sl) * NB_IN + hh * 128 + k4 * 4);
        }
        const float4* src = (const float4*)g_Bt;
        #pragma unroll
        for (int t = 0; t < 8; t++) {
            int u = tid + t * 512;
            int hh = u >> 11, rem = u & 2047;
            bR[t] = src[(hh * 128) * 64 + rem];
        }
    }

    for (int it = 0; it < 4; it++) {
        #pragma unroll
        for (int t = 0; t < 2; t++) {
            int u = tid + t * 512;
            int hh = u >> 9, rem = u & 511, row = rem & 63, k4 = rem >> 6;
            float4 v = aR[t];
            As[hh * 2048 + (k4 * 4 + 0) * 64 + row] = v.x;
            As[hh * 2048 + (k4 * 4 + 1) * 64 + row] = v.y;
            As[hh * 2048 + (k4 * 4 + 2) * 64 + row] = v.z;
            As[hh * 2048 + (k4 * 4 + 3) * 64 + row] = v.w;
        }
        #pragma unroll
        for (int t = 0; t < 8; t++) {
            int u = tid + t * 512;
            ((float4*)Bs)[u] = bR[t];
        }
        __syncthreads();

        if (it < 3) {
            int kc = (it + 1) * 32;
            #pragma unroll
            for (int t = 0; t < 2; t++) {
                int u = tid + t * 512;
                int hh = u >> 9, rem = u & 511, row = rem & 63, k4 = rem >> 6;
                int b = row >> 2, sl = row & 3;
                aR[t] = *(const float4*)(x + (b * NB_S + s0 + sl) * NB_IN + hh * 128 + kc + k4 * 4);
            }
            const float4* src = (const float4*)g_Bt;
            #pragma unroll
            for (int t = 0; t < 8; t++) {
                int u = tid + t * 512;
                int hh = u >> 11, rem = u & 2047;
                bR[t] = src[(hh * 128 + kc) * 64 + rem];
            }
        }

        const float4* As4 = (const float4*)(As + h * 2048);
        const ulonglong2* B2 = (const ulonglong2*)(Bs + h * 8192);
        #pragma unroll 4
        for (int k = 0; k < 32; k++) {
            float4 a0 = As4[k * 16 + rg * 2];
            float4 a1 = As4[k * 16 + rg * 2 + 1];
            ulonglong2 bz = B2[k * 64 + cg];
            ulonglong2 br = B2[k * 64 + 32 + cg];
            ull pa[8];
            PACK2(pa[0], a0.x); PACK2(pa[1], a0.y); PACK2(pa[2], a0.z); PACK2(pa[3], a0.w);
            PACK2(pa[4], a1.x); PACK2(pa[5], a1.y); PACK2(pa[6], a1.z); PACK2(pa[7], a1.w);
            #pragma unroll
            for (int r = 0; r < 8; r++) {
                FFMA2(accz[r][0], pa[r], bz.x);
                FFMA2(accz[r][1], pa[r], bz.y);
                FFMA2(accr[r][0], pa[r], br.x);
                FFMA2(accr[r][1], pa[r], br.y);
            }
        }
        __syncthreads();
    }

    if (h == 0) {
        #pragma unroll
        for (int r = 0; r < 8; r++) {
            int row = rg * 8 + r;
            *(ull*)(zbuf + row * 128 + cg * 4)     = accz[r][0];
            *(ull*)(zbuf + row * 128 + cg * 4 + 2) = accz[r][1];
            *(ull*)(rbuf + row * 128 + cg * 4)     = accr[r][0];
            *(ull*)(rbuf + row * 128 + cg * 4 + 2) = accr[r][1];
        }
    }
    __syncthreads();
    if (h == 1) {
        #pragma unroll
        for (int r = 0; r < 8; r++) {
            int row = rg * 8 + r;
            ull* pz = (ull*)(zbuf + row * 128 + cg * 4);
            ull* pr = (ull*)(rbuf + row * 128 + cg * 4);
            ADD2(accz[r][0], pz[0]); ADD2(accz[r][1], pz[1]);
            ADD2(accr[r][0], pr[0]); ADD2(accr[r][1], pr[1]);
            pz[0] = accz[r][0]; pz[1] = accz[r][1];
            pr[0] = accr[r][0]; pr[1] = accr[r][1];
        }
    }
    __syncthreads();

    #pragma unroll
    for (int t = 0; t < 16; t++) {
        int u = tid + t * 512;
        int row = u >> 7, i = u & 127;
        int b = row >> 2, sl = row & 3;
        g_R[(b * NB_S + s0 + sl) * NB_OUT + i] = rbuf[row * 128 + i];
    }

    {
        int g = tid >> 3, l8 = tid & 7;
        float s1 = 0.f, s2 = 0.f;
        #pragma unroll
        for (int q = 0; q < 16; q++) {
            float v = zbuf[g * 128 + l8 * 16 + q];
            s1 += v; s2 = fmaf(v, v, s2);
        }
        #pragma unroll
        for (int m = 1; m < 8; m <<= 1) {
            s1 += __shfl_xor_sync(0xffffffffu, s1, m);
            s2 += __shfl_xor_sync(0xffffffffu, s2, m);
        }
        if (l8 == 0) {
            float mu  = s1 * (1.f / 128.f);
            float var = s2 * (1.f / 128.f) - mu * mu;
            musig[g * 2]     = mu;
            musig[g * 2 + 1] = rsqrtf(var + LN_EPS);
        }
    }
    __syncthreads();

    #pragma unroll
    for (int t = 0; t < 16; t++) {
        int idx = t * 512 + tid;
        int b = idx & 15, i = (idx >> 4) & 127, s = idx >> 11;
        int row = b * 4 + s;
        float v = zbuf[row * 128 + i];
        v = (v - musig[row * 2]) * musig[row * 2 + 1] * gb[i] + gb[128 + i];
        g_Zt[s0 * 2048 + idx] = v;
    }
}

// ============================================================================
// K2: W[s,i,j] = sum_g P[i,j,g]*cos(2*pi*s/p), p = i*768+j*6+g+2 (analytic)
//     T[b,s,i] = sum_j Z[b,s,j]*W[s,i,j]
// ============================================================================
extern __shared__ float k2_sm[];
__global__ __launch_bounds__(256) void k2_mix(const float* __restrict__ P)
{
    float* Ws = k2_sm;            // [4][128][32]
    float* Zs = k2_sm + 16384;    // [4][128][16]

    const int tid = threadIdx.x;
    const int s0  = blockIdx.x * 4;
    const int i0  = blockIdx.y * 32;

    {
        const float4* src = (const float4*)(g_Zt + s0 * 2048);
        float4* dst = (float4*)Zs;
        #pragma unroll
        for (int u = tid; u < 2048; u += 256) dst[u] = src[u];
    }

    {
        const int il = tid & 31;
        const int jb = tid >> 5;
        const int ig = i0 + il;
        if (i0 == 0) {
            #pragma unroll 1
            for (int jr = 0; jr < 16; jr++) {
                int j = jb + 8 * jr;
                int pb = (ig * 128 + j) * NB_NB;
                const float* Pp = P + pb;
                float pv[NB_NB], ip[NB_NB];
                #pragma unroll
                for (int g = 0; g < NB_NB; g++) {
                    pv[g] = Pp[g];
                    ip[g] = rcpa((float)(pb + g + 2));
                }
                #pragma unroll
                for (int sl = 0; sl < 4; sl++) {
                    float sf = (float)(s0 + sl);
                    float wv = 0.f;
                    #pragma unroll
                    for (int g = 0; g < NB_NB; g++) {
                        float t = sf * ip[g];
                        t -= floorf(t);
                        wv = fmaf(pv[g], cosa(TWO_PI * t), wv);
                    }
                    Ws[(sl * 128 + j) * 32 + il] = wv;
                }
            }
        } else {
            #pragma unroll 1
            for (int jr = 0; jr < 16; jr++) {
                int j = jb + 8 * jr;
                int pb = (ig * 128 + j) * NB_NB;
                const float* Pp = P + pb;
                float pv[NB_NB], ip[NB_NB];
                #pragma unroll
                for (int g = 0; g < NB_NB; g++) {
                    pv[g] = Pp[g];
                    ip[g] = rcpa((float)(pb + g + 2)) * TWO_PI;
                }
                #pragma unroll
                for (int sl = 0; sl < 4; sl++) {
                    float sf = (float)(s0 + sl);
                    float wv = 0.f;
                    #pragma unroll
                    for (int g = 0; g < NB_NB; g++) {
                        wv = fmaf(pv[g], cosa(sf * ip[g]), wv);
                    }
                    Ws[(sl * 128 + j) * 32 + il] = wv;
                }
            }
        }
    }
    __syncthreads();

    {
        const int w  = tid >> 5;
        const int l  = tid & 31;
        const int s  = w >> 1;
        const int bh = w & 1;
        const int bq = l >> 3;
        const int iq = l & 7;
        const int b0 = bh * 8 + bq * 2;

        ull acc[2][2];
        acc[0][0] = 0ull; acc[0][1] = 0ull; acc[1][0] = 0ull; acc[1][1] = 0ull;

        const ull* Zp = (const ull*)Zs + s * 1024 + (b0 >> 1);
        const ulonglong2* Wp = (const ulonglong2*)Ws + s * 1024 + iq;
        #pragma unroll 8
        for (int j = 0; j < 128; j++) {
            ull zu = Zp[j * 8];
            float2 z = *(float2*)&zu;
            ulonglong2 wv = Wp[j * 8];
            ull pz;
            PACK2(pz, z.x); FFMA2(acc[0][0], pz, wv.x); FFMA2(acc[0][1], pz, wv.y);
            PACK2(pz, z.y); FFMA2(acc[1][0], pz, wv.x); FFMA2(acc[1][1], pz, wv.y);
        }
        int sg = s0 + s;
        #pragma unroll
        for (int bi = 0; bi < 2; bi++) {
            int b = b0 + bi;
            ulonglong2 o; o.x = acc[bi][0]; o.y = acc[bi][1];
            *(ulonglong2*)(g_T + (b * NB_S + sg) * NB_OUT + i0 + iq * 4) = o;
        }
    }
}

// ============================================================================
// K3: out[b,o,i] = sum_{k<2L} A[k,o]*Bm[b,k,i]
//     A[2s+t] = (t? res_linker : Linker)[s],  Bm[b,2s+t] = (t? g_R : g_T)[b,s]
// Block (o-tile 32, b). 512 threads = 4 o-groups x 4 k-quarters.
// Thread tile 8 o x 4 i. cp.async double-buffered chunks of 128 k (2x80KB smem).
// ============================================================================
extern __shared__ float k3_sm[];
// buf0: A @0 (4096 fl), B @4096 (16384 fl); buf1: A @20480, B @24576. 160KB.
__global__ __launch_bounds__(512) void k3_link(
    const float* __restrict__ Lk, const float* __restrict__ rLk,
    float* __restrict__ out, const int* __restrict__ pL)
{
    const uint32_t sbase = (uint32_t)__cvta_generic_to_shared(k3_sm);

    const int tid = threadIdx.x;
    const int o0 = blockIdx.x * 32;
    const int b  = blockIdx.y;
    const int L  = pL[0];
    const int Lo = (L / 2) > 1 ? (L / 2) : 1;
    const int L2 = L * 2;

    const int w  = tid >> 5;
    const int l  = tid & 31;
    const int og = w & 3;       // o-group: o = o0 + og*8 + oi
    const int q  = w >> 2;      // k-quarter

    ull acc[8][2];
    #pragma unroll
    for (int a = 0; a < 8; a++) { acc[a][0] = 0ull; acc[a][1] = 0ull; }

    // ---- cp.async issue of one 128-k chunk into buffer (c&1) ----
    auto issue = [&](int c) {
        const int buf = c & 1;
        const uint32_t Ab = sbase + (buf ? 20480u : 0u) * 4u;
        const uint32_t Bb = sbase + (buf ? 24576u : 4096u) * 4u;
        const int kc = c * 128;
        // A: 128 k x 32 o = 1024 cp16
        #pragma unroll
        for (int t = 0; t < 2; t++) {
            int u = tid + t * 512;
            int k = u >> 3, part = u & 7;
            int kg = kc + k;
            bool ok = (kg < L2);
            int sg = (kg >> 1);
            const float* src = ((kg & 1) ? rLk : Lk) + (ok ? sg : 0) * NB_SO + o0 + part * 4;
            cp16(Ab + (uint32_t)(k * 32 + part * 4) * 4u, src, ok);
        }
        // B: 128 k x 128 i = 4096 cp16
        #pragma unroll
        for (int t = 0; t < 8; t++) {
            int u = tid + t * 512;
            int k = u >> 5, part = u & 31;
            int kg = kc + k;
            bool ok = (kg < L2);
            int sg = (kg >> 1);
            const float* src = ((kg & 1) ? g_R : g_T) + ((size_t)b * NB_S + (ok ? sg : 0)) * NB_OUT + part * 4;
            cp16(Bb + (uint32_t)(k * 128 + part * 4) * 4u, src, ok);
        }
        CP_COMMIT();
    };

    issue(0);

    for (int c = 0; c < 8; c++) {
        if (c < 7) {
            issue(c + 1);
            CP_WAIT(1);     // chunk c complete (chunk c+1 may be in flight)
        } else {
            CP_WAIT(0);
        }
        __syncthreads();

        const int buf = c & 1;
        const float* A = k3_sm + (buf ? 20480 : 0);
        const float* B = k3_sm + (buf ? 24576 : 4096);

        const float4* Af = (const float4*)A + (q * 32) * 8 + og * 2;
        const ulonglong2* B2 = (const ulonglong2*)B + (q * 32) * 32 + l;
        #pragma unroll 4
        for (int k = 0; k < 32; k++) {
            float4 a0 = Af[k * 8];          // broadcast (warp-uniform)
            float4 a1 = Af[k * 8 + 1];      // broadcast
            ulonglong2 bv = B2[k * 32];
            ull pa[8];
            PACK2(pa[0], a0.x); PACK2(pa[1], a0.y); PACK2(pa[2], a0.z); PACK2(pa[3], a0.w);
            PACK2(pa[4], a1.x); PACK2(pa[5], a1.y); PACK2(pa[6], a1.z); PACK2(pa[7], a1.w);
            #pragma unroll
            for (int oi = 0; oi < 8; oi++) {
                FFMA2(acc[oi][0], pa[oi], bv.x);
                FFMA2(acc[oi][1], pa[oi], bv.y);
            }
        }
        __syncthreads();   // free this buffer for the issue 2 iterations ahead
    }

    // 4-way split-K reduction through buf0 B region (12288 fl <= 16384)
    float* red = k3_sm + 4096;
    if (q > 0) {
        ulonglong2* st = (ulonglong2*)red + ((q - 1) * 4 + og) * 256;
        #pragma unroll
        for (int oi = 0; oi < 8; oi++) {
            ulonglong2 v; v.x = acc[oi][0]; v.y = acc[oi][1];
            st[oi * 32 + l] = v;
        }
    }
    __syncthreads();
    if (q == 0) {
        #pragma unroll
        for (int oi = 0; oi < 8; oi++) {
            #pragma unroll
            for (int qq = 0; qq < 3; qq++) {
                ulonglong2 v = ((const ulonglong2*)red)[(qq * 4 + og) * 256 + oi * 32 + l];
                ADD2(acc[oi][0], v.x);
                ADD2(acc[oi][1], v.y);
            }
            int o = o0 + og * 8 + oi;
            if (o < Lo) {
                ulonglong2 ov; ov.x = acc[oi][0]; ov.y = acc[oi][1];
                *(ulonglong2*)(out + (b * Lo + o) * NB_OUT + l * 4) = ov;
            }
        }
    }
}

// ============================================================================
extern "C" void kernel_launch(void* const* d_in, const int* in_sizes, int n_in,
                              void* d_out, int out_size)
{
    const float* x    = (const float*)d_in[0];
    const float* M    = (const float*)d_in[1];
    const float* P    = (const float*)d_in[2];
    const float* Lk   = (const float*)d_in[3];
    const float* lng  = (const float*)d_in[4];
    const float* lnb  = (const float*)d_in[5];
    const float* rW   = (const float*)d_in[6];
    const float* rLk  = (const float*)d_in[7];
    const int*   pL   = (const int*)d_in[9];
    float* out = (float*)d_out;

    cudaFuncSetAttribute(k1_proj_ln, cudaFuncAttributeMaxDynamicSharedMemorySize, 84992);
    cudaFuncSetAttribute(k2_mix,     cudaFuncAttributeMaxDynamicSharedMemorySize, 98304);
    cudaFuncSetAttribute(k3_link,    cudaFuncAttributeMaxDynamicSharedMemorySize, 163840);

    k0_transpose<<<dim3(8, 8), 256>>>(M, rW);
    k1_proj_ln<<<NB_S / 4, 512, 84992>>>(x, lng, lnb);
    k2_mix<<<dim3(NB_S / 4, NB_OUT / 32), 256, 98304>>>(P);
    k3_link<<<dim3(8, NB_B), 512, 163840>>>(Lk, rLk, out, pL);
}

// round 15
// speedup vs baseline: 1.7314x; 1.0408x over previous
#include <cuda_runtime.h>
#include <cstdint>
#include <math.h>

// ---- problem constants ----
#define NB_B   16
#define NB_S   512
#define NB_IN  256
#define NB_OUT 128
#define NB_NB  6
#define NB_SO  256
#define LN_EPS 1e-5f
#define TWO_PI 6.283185307179586f

typedef unsigned long long ull;

// ---- scratch ----
__device__ float g_Zt[NB_S * NB_OUT * NB_B];   // [s][j][b]
__device__ float g_R [NB_B * NB_S * NB_OUT];   // [b][s][i]
__device__ float g_T [NB_B * NB_S * NB_OUT];   // [b][s][i]
__device__ float g_Bt[NB_IN * 256];            // [k][n]  n<128: M, n>=128: res_W

__device__ __forceinline__ float cosa(float x) {
    float r; asm("cos.approx.f32 %0, %1;" : "=f"(r) : "f"(x)); return r;
}
__device__ __forceinline__ float rcpa(float x) {
    float r; asm("rcp.approx.f32 %0, %1;" : "=f"(r) : "f"(x)); return r;
}
#define FFMA2(d, a, b) asm("fma.rn.f32x2 %0, %1, %2, %0;" : "+l"(d) : "l"(a), "l"(b))
#define ADD2(d, a)     asm("add.rn.f32x2 %0, %0, %1;"     : "+l"(d) : "l"(a))
#define PACK2(d, f)    asm("mov.b64 %0, {%1, %1};" : "=l"(d) : "f"(f))

// cp.async 16B with zero-fill predicate (src-size 0 when pred false)
__device__ __forceinline__ void cp16(uint32_t dst, const void* src, bool pred) {
    int sz = pred ? 16 : 0;
    asm volatile("cp.async.cg.shared.global [%0], [%1], 16, %2;"
                 :: "r"(dst), "l"(src), "r"(sz));
}
#define CP_COMMIT() asm volatile("cp.async.commit_group;" ::: "memory")
#define CP_WAIT(n)  asm volatile("cp.async.wait_group %0;" :: "n"(n) : "memory")

// ============================================================================
// K0: transpose [M; res_W] -> g_Bt[k][n]
// ============================================================================
__global__ __launch_bounds__(256) void k0_transpose(
    const float* __restrict__ M, const float* __restrict__ rW)
{
    __shared__ float t[32][33];
    const int k0 = blockIdx.x * 32;
    const int n0 = blockIdx.y * 32;
    const int lx = threadIdx.x & 31, ly = threadIdx.x >> 5;

    #pragma unroll
    for (int r = 0; r < 32; r += 8) {
        int n = n0 + ly + r;
        const float* src = (n < 128) ? (M + n * NB_IN) : (rW + (n - 128) * NB_IN);
        t[ly + r][lx] = src[k0 + lx];
    }
    __syncthreads();
    #pragma unroll
    for (int r = 0; r < 32; r += 8) {
        g_Bt[(k0 + ly + r) * 256 + n0 + lx] = t[lx][ly + r];
    }
}

// ============================================================================
// K1: Z = LN(x @ M^T) -> g_Zt[s][j][b],  R = x @ res_W^T -> g_R[b][s][i]
// Block: 64 rows (16 b x 4 s) x 256 cols. 512 threads, split-K halves.
// A (x tile) loaded ONCE k-major (64KB). B (g_Bt) cp.async double-buffered
// 64KB chunks of 32 k x both halves. Thread tile 8 rows x (4z + 4r cols).
// ============================================================================
extern __shared__ float k1_sm[];
// As_full [2 h][128 k][64 row] @0      (16384 fl, 64KB)  -- aliased by zbuf/rbuf later
// Bs0     [2 h][32 k][256 n]  @16384  (16384 fl, 64KB)
// Bs1                          @32768  (16384 fl, 64KB)
// musig [64][2] @49152 (128) | gb @49280 (256)   => 49536 fl = 198144 B
__global__ __launch_bounds__(512) void k1_proj_ln(
    const float* __restrict__ x, const float* __restrict__ lng,
    const float* __restrict__ lnb)
{
    float* As    = k1_sm;
    float* zbuf  = k1_sm;
    float* rbuf  = k1_sm + 8192;
    float* musig = k1_sm + 49152;
    float* gb    = k1_sm + 49280;
    const uint32_t sbase = (uint32_t)__cvta_generic_to_shared(k1_sm);

    const int tid = threadIdx.x;
    const int s0  = blockIdx.x * 4;
    const int w   = tid >> 5;
    const int l   = tid & 31;
    const int h   = w >> 3;     // k-half
    const int rg  = w & 7;      // rows rg*8..+7
    const int cg  = l;          // cols cg*4 (z) / +128 (r)

    if (tid < 128) gb[tid] = lng[tid];
    else if (tid < 256) gb[tid] = lnb[tid - 128];

    // ---- B chunk issue via cp.async: chunk c = k rows [c*32, c*32+32) of both halves
    auto issueB = [&](int c) {
        const uint32_t Bb = sbase + (uint32_t)(16384 + (c & 1) * 16384) * 4u;
        const int kc = c * 32;
        #pragma unroll
        for (int t = 0; t < 8; t++) {
            int u = tid + t * 512;              // 0..4095
            int hh = u >> 11, rem = u & 2047;
            int k = rem >> 6, part = rem & 63;  // part: 64 f4 per k-row
            const float* src = g_Bt + (hh * 128 + kc + k) * 256 + part * 4;
            cp16(Bb + (uint32_t)(hh * 8192 + k * 256 + part * 4) * 4u, src, true);
        }
        CP_COMMIT();
    };

    issueB(0);
    issueB(1);

    // ---- load FULL A tile k-major (overlaps with B chunk 0/1 in flight) ----
    #pragma unroll
    for (int kcu = 0; kcu < 4; kcu++) {
        int kc = kcu * 32;
        #pragma unroll
        for (int t = 0; t < 2; t++) {
            int u = tid + t * 512;
            int hh = u >> 9, rem = u & 511, row = rem & 63, k4 = rem >> 6;
            int b = row >> 2, sl = row & 3;
            float4 v = *(const float4*)(x + (b * NB_S + s0 + sl) * NB_IN + hh * 128 + kc + k4 * 4);
            As[hh * 8192 + (kc + k4 * 4 + 0) * 64 + row] = v.x;
            As[hh * 8192 + (kc + k4 * 4 + 1) * 64 + row] = v.y;
            As[hh * 8192 + (kc + k4 * 4 + 2) * 64 + row] = v.z;
            As[hh * 8192 + (kc + k4 * 4 + 3) * 64 + row] = v.w;
        }
    }

    ull accz[8][2], accr[8][2];
    #pragma unroll
    for (int r = 0; r < 8; r++) {
        accz[r][0] = 0ull; accz[r][1] = 0ull;
        accr[r][0] = 0ull; accr[r][1] = 0ull;
    }

    for (int c = 0; c < 4; c++) {
        if (c < 3) CP_WAIT(1); else CP_WAIT(0);
        __syncthreads();    // chunk c ready; A tile ready (c==0)

        const float4* As4 = (const float4*)(As + h * 8192 + (c * 32) * 64);
        const ulonglong2* B2 = (const ulonglong2*)(k1_sm + 16384 + (c & 1) * 16384 + h * 8192);
        #pragma unroll 4
        for (int k = 0; k < 32; k++) {
            float4 a0 = As4[k * 16 + rg * 2];
            float4 a1 = As4[k * 16 + rg * 2 + 1];
            ulonglong2 bz = B2[k * 64 + cg];
            ulonglong2 br = B2[k * 64 + 32 + cg];
            ull pa[8];
            PACK2(pa[0], a0.x); PACK2(pa[1], a0.y); PACK2(pa[2], a0.z); PACK2(pa[3], a0.w);
            PACK2(pa[4], a1.x); PACK2(pa[5], a1.y); PACK2(pa[6], a1.z); PACK2(pa[7], a1.w);
            #pragma unroll
            for (int r = 0; r < 8; r++) {
                FFMA2(accz[r][0], pa[r], bz.x);
                FFMA2(accz[r][1], pa[r], bz.y);
                FFMA2(accr[r][0], pa[r], br.x);
                FFMA2(accr[r][1], pa[r], br.y);
            }
        }
        __syncthreads();    // buffer (c&1) free
        if (c < 2) issueB(c + 2);
    }

    // combine halves through zbuf/rbuf (aliases As; GEMM reads are done)
    if (h == 0) {
        #pragma unroll
        for (int r = 0; r < 8; r++) {
            int row = rg * 8 + r;
            *(ull*)(zbuf + row * 128 + cg * 4)     = accz[r][0];
            *(ull*)(zbuf + row * 128 + cg * 4 + 2) = accz[r][1];
            *(ull*)(rbuf + row * 128 + cg * 4)     = accr[r][0];
            *(ull*)(rbuf + row * 128 + cg * 4 + 2) = accr[r][1];
        }
    }
    __syncthreads();
    if (h == 1) {
        #pragma unroll
        for (int r = 0; r < 8; r++) {
            int row = rg * 8 + r;
            ull* pz = (ull*)(zbuf + row * 128 + cg * 4);
            ull* pr = (ull*)(rbuf + row * 128 + cg * 4);
            ADD2(accz[r][0], pz[0]); ADD2(accz[r][1], pz[1]);
            ADD2(accr[r][0], pr[0]); ADD2(accr[r][1], pr[1]);
            pz[0] = accz[r][0]; pz[1] = accz[r][1];
            pr[0] = accr[r][0]; pr[1] = accr[r][1];
        }
    }
    __syncthreads();

    // residual store
    #pragma unroll
    for (int t = 0; t < 16; t++) {
        int u = tid + t * 512;
        int row = u >> 7, i = u & 127;
        int b = row >> 2, sl = row & 3;
        g_R[(b * NB_S + s0 + sl) * NB_OUT + i] = rbuf[row * 128 + i];
    }

    // LN stats: 64 rows x 8 threads
    {
        int g = tid >> 3, l8 = tid & 7;
        float s1 = 0.f, s2 = 0.f;
        #pragma unroll
        for (int q = 0; q < 16; q++) {
            float v = zbuf[g * 128 + l8 * 16 + q];
            s1 += v; s2 = fmaf(v, v, s2);
        }
        #pragma unroll
        for (int m = 1; m < 8; m <<= 1) {
            s1 += __shfl_xor_sync(0xffffffffu, s1, m);
            s2 += __shfl_xor_sync(0xffffffffu, s2, m);
        }
        if (l8 == 0) {
            float mu  = s1 * (1.f / 128.f);
            float var = s2 * (1.f / 128.f) - mu * mu;
            musig[g * 2]     = mu;
            musig[g * 2 + 1] = rsqrtf(var + LN_EPS);
        }
    }
    __syncthreads();

    // normalize + transposed store g_Zt[s][j][b]
    #pragma unroll
    for (int t = 0; t < 16; t++) {
        int idx = t * 512 + tid;
        int b = idx & 15, i = (idx >> 4) & 127, s = idx >> 11;
        int row = b * 4 + s;
        float v = zbuf[row * 128 + i];
        v = (v - musig[row * 2]) * musig[row * 2 + 1] * gb[i] + gb[128 + i];
        g_Zt[s0 * 2048 + idx] = v;
    }
}

// ============================================================================
// K2: W[s,i,j] = sum_g P[i,j,g]*cos(2*pi*s/p), p = i*768+j*6+g+2 (analytic)
//     T[b,s,i] = sum_j Z[b,s,j]*W[s,i,j]   (unchanged from R12)
// ============================================================================
extern __shared__ float k2_sm[];
__global__ __launch_bounds__(256) void k2_mix(const float* __restrict__ P)
{
    float* Ws = k2_sm;            // [4][128][32]
    float* Zs = k2_sm + 16384;    // [4][128][16]

    const int tid = threadIdx.x;
    const int s0  = blockIdx.x * 4;
    const int i0  = blockIdx.y * 32;

    {
        const float4* src = (const float4*)(g_Zt + s0 * 2048);
        float4* dst = (float4*)Zs;
        #pragma unroll
        for (int u = tid; u < 2048; u += 256) dst[u] = src[u];
    }

    {
        const int il = tid & 31;
        const int jb = tid >> 5;
        const int ig = i0 + il;
        if (i0 == 0) {
            #pragma unroll 1
            for (int jr = 0; jr < 16; jr++) {
                int j = jb + 8 * jr;
                int pb = (ig * 128 + j) * NB_NB;
                const float* Pp = P + pb;
                float pv[NB_NB], ip[NB_NB];
                #pragma unroll
                for (int g = 0; g < NB_NB; g++) {
                    pv[g] = Pp[g];
                    ip[g] = rcpa((float)(pb + g + 2));
                }
                #pragma unroll
                for (int sl = 0; sl < 4; sl++) {
                    float sf = (float)(s0 + sl);
                    float wv = 0.f;
                    #pragma unroll
                    for (int g = 0; g < NB_NB; g++) {
                        float t = sf * ip[g];
                        t -= floorf(t);
                        wv = fmaf(pv[g], cosa(TWO_PI * t), wv);
                    }
                    Ws[(sl * 128 + j) * 32 + il] = wv;
                }
            }
        } else {
            #pragma unroll 1
            for (int jr = 0; jr < 16; jr++) {
                int j = jb + 8 * jr;
                int pb = (ig * 128 + j) * NB_NB;
                const float* Pp = P + pb;
                float pv[NB_NB], ip[NB_NB];
                #pragma unroll
                for (int g = 0; g < NB_NB; g++) {
                    pv[g] = Pp[g];
                    ip[g] = rcpa((float)(pb + g + 2)) * TWO_PI;
                }
                #pragma unroll
                for (int sl = 0; sl < 4; sl++) {
                    float sf = (float)(s0 + sl);
                    float wv = 0.f;
                    #pragma unroll
                    for (int g = 0; g < NB_NB; g++) {
                        wv = fmaf(pv[g], cosa(sf * ip[g]), wv);
                    }
                    Ws[(sl * 128 + j) * 32 + il] = wv;
                }
            }
        }
    }
    __syncthreads();

    {
        const int w  = tid >> 5;
        const int l  = tid & 31;
        const int s  = w >> 1;
        const int bh = w & 1;
        const int bq = l >> 3;
        const int iq = l & 7;
        const int b0 = bh * 8 + bq * 2;

        ull acc[2][2];
        acc[0][0] = 0ull; acc[0][1] = 0ull; acc[1][0] = 0ull; acc[1][1] = 0ull;

        const ull* Zp = (const ull*)Zs + s * 1024 + (b0 >> 1);
        const ulonglong2* Wp = (const ulonglong2*)Ws + s * 1024 + iq;
        #pragma unroll 8
        for (int j = 0; j < 128; j++) {
            ull zu = Zp[j * 8];
            float2 z = *(float2*)&zu;
            ulonglong2 wv = Wp[j * 8];
            ull pz;
            PACK2(pz, z.x); FFMA2(acc[0][0], pz, wv.x); FFMA2(acc[0][1], pz, wv.y);
            PACK2(pz, z.y); FFMA2(acc[1][0], pz, wv.x); FFMA2(acc[1][1], pz, wv.y);
        }
        int sg = s0 + s;
        #pragma unroll
        for (int bi = 0; bi < 2; bi++) {
            int b = b0 + bi;
            ulonglong2 o; o.x = acc[bi][0]; o.y = acc[bi][1];
            *(ulonglong2*)(g_T + (b * NB_S + sg) * NB_OUT + i0 + iq * 4) = o;
        }
    }
}

// ============================================================================
// K3 (unchanged from R12): cp.async double-buffered, 4 o-groups x 4 k-quarters,
// thread tile 8 o x 4 i.
// ============================================================================
extern __shared__ float k3_sm[];
__global__ __launch_bounds__(512) void k3_link(
    const float* __restrict__ Lk, const float* __restrict__ rLk,
    float* __restrict__ out, const int* __restrict__ pL)
{
    const uint32_t sbase = (uint32_t)__cvta_generic_to_shared(k3_sm);

    const int tid = threadIdx.x;
    const int o0 = blockIdx.x * 32;
    const int b  = blockIdx.y;
    const int L  = pL[0];
    const int Lo = (L / 2) > 1 ? (L / 2) : 1;
    const int L2 = L * 2;

    const int w  = tid >> 5;
    const int l  = tid & 31;
    const int og = w & 3;
    const int q  = w >> 2;

    ull acc[8][2];
    #pragma unroll
    for (int a = 0; a < 8; a++) { acc[a][0] = 0ull; acc[a][1] = 0ull; }

    auto issue = [&](int c) {
        const int buf = c & 1;
        const uint32_t Ab = sbase + (buf ? 20480u : 0u) * 4u;
        const uint32_t Bb = sbase + (buf ? 24576u : 4096u) * 4u;
        const int kc = c * 128;
        #pragma unroll
        for (int t = 0; t < 2; t++) {
            int u = tid + t * 512;
            int k = u >> 3, part = u & 7;
            int kg = kc + k;
            bool ok = (kg < L2);
            int sg = (kg >> 1);
            const float* src = ((kg & 1) ? rLk : Lk) + (ok ? sg : 0) * NB_SO + o0 + part * 4;
            cp16(Ab + (uint32_t)(k * 32 + part * 4) * 4u, src, ok);
        }
        #pragma unroll
        for (int t = 0; t < 8; t++) {
            int u = tid + t * 512;
            int k = u >> 5, part = u & 31;
            int kg = kc + k;
            bool ok = (kg < L2);
            int sg = (kg >> 1);
            const float* src = ((kg & 1) ? g_R : g_T) + ((size_t)b * NB_S + (ok ? sg : 0)) * NB_OUT + part * 4;
            cp16(Bb + (uint32_t)(k * 128 + part * 4) * 4u, src, ok);
        }
        CP_COMMIT();
    };

    issue(0);

    for (int c = 0; c < 8; c++) {
        if (c < 7) {
            issue(c + 1);
            CP_WAIT(1);
        } else {
            CP_WAIT(0);
        }
        __syncthreads();

        const int buf = c & 1;
        const float* A = k3_sm + (buf ? 20480 : 0);
        const float* B = k3_sm + (buf ? 24576 : 4096);

        const float4* Af = (const float4*)A + (q * 32) * 8 + og * 2;
        const ulonglong2* B2 = (const ulonglong2*)B + (q * 32) * 32 + l;
        #pragma unroll 4
        for (int k = 0; k < 32; k++) {
            float4 a0 = Af[k * 8];
            float4 a1 = Af[k * 8 + 1];
            ulonglong2 bv = B2[k * 32];
            ull pa[8];
            PACK2(pa[0], a0.x); PACK2(pa[1], a0.y); PACK2(pa[2], a0.z); PACK2(pa[3], a0.w);
            PACK2(pa[4], a1.x); PACK2(pa[5], a1.y); PACK2(pa[6], a1.z); PACK2(pa[7], a1.w);
            #pragma unroll
            for (int oi = 0; oi < 8; oi++) {
                FFMA2(acc[oi][0], pa[oi], bv.x);
                FFMA2(acc[oi][1], pa[oi], bv.y);
            }
        }
        __syncthreads();
    }

    float* red = k3_sm + 4096;
    if (q > 0) {
        ulonglong2* st = (ulonglong2*)red + ((q - 1) * 4 + og) * 256;
        #pragma unroll
        for (int oi = 0; oi < 8; oi++) {
            ulonglong2 v; v.x = acc[oi][0]; v.y = acc[oi][1];
            st[oi * 32 + l] = v;
        }
    }
    __syncthreads();
    if (q == 0) {
        #pragma unroll
        for (int oi = 0; oi < 8; oi++) {
            #pragma unroll
            for (int qq = 0; qq < 3; qq++) {
                ulonglong2 v = ((const ulonglong2*)red)[(qq * 4 + og) * 256 + oi * 32 + l];
                ADD2(acc[oi][0], v.x);
                ADD2(acc[oi][1], v.y);
            }
            int o = o0 + og * 8 + oi;
            if (o < Lo) {
                ulonglong2 ov; ov.x = acc[oi][0]; ov.y = acc[oi][1];
                *(ulonglong2*)(out + (b * Lo + o) * NB_OUT + l * 4) = ov;
            }
        }
    }
}

// ============================================================================
extern "C" void kernel_launch(void* const* d_in, const int* in_sizes, int n_in,
                              void* d_out, int out_size)
{
    const float* x    = (const float*)d_in[0];
    const float* M    = (const float*)d_in[1];
    const float* P    = (const float*)d_in[2];
    const float* Lk   = (const float*)d_in[3];
    const float* lng  = (const float*)d_in[4];
    const float* lnb  = (const float*)d_in[5];
    const float* rW   = (const float*)d_in[6];
    const float* rLk  = (const float*)d_in[7];
    const int*   pL   = (const int*)d_in[9];
    float* out = (float*)d_out;

    cudaFuncSetAttribute(k1_proj_ln, cudaFuncAttributeMaxDynamicSharedMemorySize, 198144);
    cudaFuncSetAttribute(k2_mix,     cudaFuncAttributeMaxDynamicSharedMemorySize, 98304);
    cudaFuncSetAttribute(k3_link,    cudaFuncAttributeMaxDynamicSharedMemorySize, 163840);

    k0_transpose<<<dim3(8, 8), 256>>>(M, rW);
    k1_proj_ln<<<NB_S / 4, 512, 198144>>>(x, lng, lnb);
    k2_mix<<<dim3(NB_S / 4, NB_OUT / 32), 256, 98304>>>(P);
    k3_link<<<dim3(8, NB_B), 512, 163840>>>(Lk, rLk, out, pL);
}

// round 17
// speedup vs baseline: 2.2341x; 1.2903x over previous
#include <cuda_runtime.h>
#include <cstdint>
#include <math.h>

// ---- problem constants ----
#define NB_B   16
#define NB_S   512
#define NB_IN  256
#define NB_OUT 128
#define NB_NB  6
#define NB_SO  256
#define LN_EPS 1e-5f
#define TWO_PI 6.283185307179586f

typedef unsigned long long ull;

// ---- scratch ----
__device__ float g_Zt[NB_S * NB_OUT * NB_B];   // [s][j][b]
__device__ float g_R [NB_B * NB_S * NB_OUT];   // [b][s][i]
__device__ float g_T [NB_B * NB_S * NB_OUT];   // [b][s][i]
__device__ float g_Bt[NB_IN * 256];            // [k][n]  n<128: M, n>=128: res_W

__device__ __forceinline__ float cosa(float x) {
    float r; asm("cos.approx.f32 %0, %1;" : "=f"(r) : "f"(x)); return r;
}
__device__ __forceinline__ float rcpa(float x) {
    float r; asm("rcp.approx.f32 %0, %1;" : "=f"(r) : "f"(x)); return r;
}
#define FFMA2(d, a, b) asm("fma.rn.f32x2 %0, %1, %2, %0;" : "+l"(d) : "l"(a), "l"(b))
#define ADD2(d, a)     asm("add.rn.f32x2 %0, %0, %1;"     : "+l"(d) : "l"(a))
#define PACK2(d, f)    asm("mov.b64 %0, {%1, %1};" : "=l"(d) : "f"(f))

// cp.async 16B with zero-fill predicate (src-size 0 when pred false)
__device__ __forceinline__ void cp16(uint32_t dst, const void* src, bool pred) {
    int sz = pred ? 16 : 0;
    asm volatile("cp.async.cg.shared.global [%0], [%1], 16, %2;"
                 :: "r"(dst), "l"(src), "r"(sz));
}
#define CP_COMMIT() asm volatile("cp.async.commit_group;" ::: "memory")
#define CP_WAIT(n)  asm volatile("cp.async.wait_group %0;" :: "n"(n) : "memory")

// ============================================================================
// K0: transpose [M; res_W] -> g_Bt[k][n]
// ============================================================================
__global__ __launch_bounds__(256) void k0_transpose(
    const float* __restrict__ M, const float* __restrict__ rW)
{
    __shared__ float t[32][33];
    const int k0 = blockIdx.x * 32;
    const int n0 = blockIdx.y * 32;
    const int lx = threadIdx.x & 31, ly = threadIdx.x >> 5;

    #pragma unroll
    for (int r = 0; r < 32; r += 8) {
        int n = n0 + ly + r;
        const float* src = (n < 128) ? (M + n * NB_IN) : (rW + (n - 128) * NB_IN);
        t[ly + r][lx] = src[k0 + lx];
    }
    __syncthreads();
    #pragma unroll
    for (int r = 0; r < 32; r += 8) {
        g_Bt[(k0 + ly + r) * 256 + n0 + lx] = t[lx][ly + r];
    }
}

// ============================================================================
// K1: Z = LN(x @ M^T) -> g_Zt[s][j][b],  R = x @ res_W^T -> g_R[b][s][i]
// (unchanged from R15)
// ============================================================================
extern __shared__ float k1_sm[];
__global__ __launch_bounds__(512) void k1_proj_ln(
    const float* __restrict__ x, const float* __restrict__ lng,
    const float* __restrict__ lnb)
{
    float* As    = k1_sm;
    float* zbuf  = k1_sm;
    float* rbuf  = k1_sm + 8192;
    float* musig = k1_sm + 49152;
    float* gb    = k1_sm + 49280;
    const uint32_t sbase = (uint32_t)__cvta_generic_to_shared(k1_sm);

    const int tid = threadIdx.x;
    const int s0  = blockIdx.x * 4;
    const int w   = tid >> 5;
    const int l   = tid & 31;
    const int h   = w >> 3;
    const int rg  = w & 7;
    const int cg  = l;

    if (tid < 128) gb[tid] = lng[tid];
    else if (tid < 256) gb[tid] = lnb[tid - 128];

    auto issueB = [&](int c) {
        const uint32_t Bb = sbase + (uint32_t)(16384 + (c & 1) * 16384) * 4u;
        const int kc = c * 32;
        #pragma unroll
        for (int t = 0; t < 8; t++) {
            int u = tid + t * 512;
            int hh = u >> 11, rem = u & 2047;
            int k = rem >> 6, part = rem & 63;
            const float* src = g_Bt + (hh * 128 + kc + k) * 256 + part * 4;
            cp16(Bb + (uint32_t)(hh * 8192 + k * 256 + part * 4) * 4u, src, true);
        }
        CP_COMMIT();
    };

    issueB(0);
    issueB(1);

    #pragma unroll
    for (int kcu = 0; kcu < 4; kcu++) {
        int kc = kcu * 32;
        #pragma unroll
        for (int t = 0; t < 2; t++) {
            int u = tid + t * 512;
            int hh = u >> 9, rem = u & 511, row = rem & 63, k4 = rem >> 6;
            int b = row >> 2, sl = row & 3;
            float4 v = *(const float4*)(x + (b * NB_S + s0 + sl) * NB_IN + hh * 128 + kc + k4 * 4);
            As[hh * 8192 + (kc + k4 * 4 + 0) * 64 + row] = v.x;
            As[hh * 8192 + (kc + k4 * 4 + 1) * 64 + row] = v.y;
            As[hh * 8192 + (kc + k4 * 4 + 2) * 64 + row] = v.z;
            As[hh * 8192 + (kc + k4 * 4 + 3) * 64 + row] = v.w;
        }
    }

    ull accz[8][2], accr[8][2];
    #pragma unroll
    for (int r = 0; r < 8; r++) {
        accz[r][0] = 0ull; accz[r][1] = 0ull;
        accr[r][0] = 0ull; accr[r][1] = 0ull;
    }

    for (int c = 0; c < 4; c++) {
        if (c < 3) CP_WAIT(1); else CP_WAIT(0);
        __syncthreads();

        const float4* As4 = (const float4*)(As + h * 8192 + (c * 32) * 64);
        const ulonglong2* B2 = (const ulonglong2*)(k1_sm + 16384 + (c & 1) * 16384 + h * 8192);
        #pragma unroll 4
        for (int k = 0; k < 32; k++) {
            float4 a0 = As4[k * 16 + rg * 2];
            float4 a1 = As4[k * 16 + rg * 2 + 1];
            ulonglong2 bz = B2[k * 64 + cg];
            ulonglong2 br = B2[k * 64 + 32 + cg];
            ull pa[8];
            PACK2(pa[0], a0.x); PACK2(pa[1], a0.y); PACK2(pa[2], a0.z); PACK2(pa[3], a0.w);
            PACK2(pa[4], a1.x); PACK2(pa[5], a1.y); PACK2(pa[6], a1.z); PACK2(pa[7], a1.w);
            #pragma unroll
            for (int r = 0; r < 8; r++) {
                FFMA2(accz[r][0], pa[r], bz.x);
                FFMA2(accz[r][1], pa[r], bz.y);
                FFMA2(accr[r][0], pa[r], br.x);
                FFMA2(accr[r][1], pa[r], br.y);
            }
        }
        __syncthreads();
        if (c < 2) issueB(c + 2);
    }

    if (h == 0) {
        #pragma unroll
        for (int r = 0; r < 8; r++) {
            int row = rg * 8 + r;
            *(ull*)(zbuf + row * 128 + cg * 4)     = accz[r][0];
            *(ull*)(zbuf + row * 128 + cg * 4 + 2) = accz[r][1];
            *(ull*)(rbuf + row * 128 + cg * 4)     = accr[r][0];
            *(ull*)(rbuf + row * 128 + cg * 4 + 2) = accr[r][1];
        }
    }
    __syncthreads();
    if (h == 1) {
        #pragma unroll
        for (int r = 0; r < 8; r++) {
            int row = rg * 8 + r;
            ull* pz = (ull*)(zbuf + row * 128 + cg * 4);
            ull* pr = (ull*)(rbuf + row * 128 + cg * 4);
            ADD2(accz[r][0], pz[0]); ADD2(accz[r][1], pz[1]);
            ADD2(accr[r][0], pr[0]); ADD2(accr[r][1], pr[1]);
            pz[0] = accz[r][0]; pz[1] = accz[r][1];
            pr[0] = accr[r][0]; pr[1] = accr[r][1];
        }
    }
    __syncthreads();

    #pragma unroll
    for (int t = 0; t < 16; t++) {
        int u = tid + t * 512;
        int row = u >> 7, i = u & 127;
        int b = row >> 2, sl = row & 3;
        g_R[(b * NB_S + s0 + sl) * NB_OUT + i] = rbuf[row * 128 + i];
    }

    {
        int g = tid >> 3, l8 = tid & 7;
        float s1 = 0.f, s2 = 0.f;
        #pragma unroll
        for (int q = 0; q < 16; q++) {
            float v = zbuf[g * 128 + l8 * 16 + q];
            s1 += v; s2 = fmaf(v, v, s2);
        }
        #pragma unroll
        for (int m = 1; m < 8; m <<= 1) {
            s1 += __shfl_xor_sync(0xffffffffu, s1, m);
            s2 += __shfl_xor_sync(0xffffffffu, s2, m);
        }
        if (l8 == 0) {
            float mu  = s1 * (1.f / 128.f);
            float var = s2 * (1.f / 128.f) - mu * mu;
            musig[g * 2]     = mu;
            musig[g * 2 + 1] = rsqrtf(var + LN_EPS);
        }
    }
    __syncthreads();

    #pragma unroll
    for (int t = 0; t < 16; t++) {
        int idx = t * 512 + tid;
        int b = idx & 15, i = (idx >> 4) & 127, s = idx >> 11;
        int row = b * 4 + s;
        float v = zbuf[row * 128 + i];
        v = (v - musig[row * 2]) * musig[row * 2 + 1] * gb[i] + gb[128 + i];
        g_Zt[s0 * 2048 + idx] = v;
    }
}

// ============================================================================
// K2: W[s,i,j] = sum_g P[i,j,g]*cos(2*pi*s/p), p = i*768+j*6+g+2 (analytic)
//     T[b,s,i] = sum_j Z[b,s,j]*W[s,i,j]
// NEW: P staged through smem in 4 j-chunks (coalesced LDG; stride-201 rows
// make lane reads conflict-free). Zs loaded after phase 1 (same smem region).
// ============================================================================
extern __shared__ float k2_sm[];
__global__ __launch_bounds__(256) void k2_mix(const float* __restrict__ P)
{
    float* Ws = k2_sm;            // [4][128][32] = 16384 fl
    float* Ps = k2_sm + 16384;    // [32][201] fl = 6432 fl (phase 1)
    float* Zs = k2_sm + 16384;    // [4][128][16] = 8192 fl (phase 2)

    const int tid = threadIdx.x;
    const int s0  = blockIdx.x * 4;
    const int i0  = blockIdx.y * 32;

    const int il = tid & 31;
    const int jb = tid >> 5;
    const int ig = i0 + il;

    // ---- phase 1: generate W tile, P staged per 32-j chunk ----
    for (int jc = 0; jc < 4; jc++) {
        // cooperative coalesced load: rows i0..i0+31, 192 contiguous floats each
        #pragma unroll
        for (int t = 0; t < 24; t++) {
            int u = tid + t * 256;            // 0..6143
            int row = u / 192, col = u - row * 192;
            Ps[row * 201 + col] = P[(i0 + row) * 768 + jc * 192 + col];
        }
        __syncthreads();

        if (i0 == 0) {
            #pragma unroll
            for (int jl = 0; jl < 4; jl++) {
                int jloc = jb + 8 * jl;
                int j = jc * 32 + jloc;
                int pb = (ig * 128 + j) * NB_NB;
                const float* Pp = Ps + il * 201 + jloc * 6;
                float pv[NB_NB], ip[NB_NB];
                #pragma unroll
                for (int g = 0; g < NB_NB; g++) {
                    pv[g] = Pp[g];
                    ip[g] = rcpa((float)(pb + g + 2));
                }
                #pragma unroll
                for (int sl = 0; sl < 4; sl++) {
                    float sf = (float)(s0 + sl);
                    float wv = 0.f;
                    #pragma unroll
                    for (int g = 0; g < NB_NB; g++) {
                        float t = sf * ip[g];
                        t -= floorf(t);
                        wv = fmaf(pv[g], cosa(TWO_PI * t), wv);
                    }
                    Ws[(sl * 128 + j) * 32 + il] = wv;
                }
            }
        } else {
            #pragma unroll
            for (int jl = 0; jl < 4; jl++) {
                int jloc = jb + 8 * jl;
                int j = jc * 32 + jloc;
                int pb = (ig * 128 + j) * NB_NB;
                const float* Pp = Ps + il * 201 + jloc * 6;
                float pv[NB_NB], ip[NB_NB];
                #pragma unroll
                for (int g = 0; g < NB_NB; g++) {
                    pv[g] = Pp[g];
                    ip[g] = rcpa((float)(pb + g + 2)) * TWO_PI;
                }
                #pragma unroll
                for (int sl = 0; sl < 4; sl++) {
                    float sf = (float)(s0 + sl);
                    float wv = 0.f;
                    #pragma unroll
                    for (int g = 0; g < NB_NB; g++) {
                        wv = fmaf(pv[g], cosa(sf * ip[g]), wv);
                    }
                    Ws[(sl * 128 + j) * 32 + il] = wv;
                }
            }
        }
        __syncthreads();   // Ps free for next chunk
    }

    // ---- load Z tile (overwrites Ps region) ----
    {
        const float4* src = (const float4*)(g_Zt + s0 * 2048);
        float4* dst = (float4*)Zs;
        #pragma unroll
        for (int u = tid; u < 2048; u += 256) dst[u] = src[u];
    }
    __syncthreads();

    // ---- phase 2: GEMM (unchanged) ----
    {
        const int w  = tid >> 5;
        const int l  = tid & 31;
        const int s  = w >> 1;
        const int bh = w & 1;
        const int bq = l >> 3;
        const int iq = l & 7;
        const int b0 = bh * 8 + bq * 2;

        ull acc[2][2];
        acc[0][0] = 0ull; acc[0][1] = 0ull; acc[1][0] = 0ull; acc[1][1] = 0ull;

        const ull* Zp = (const ull*)Zs + s * 1024 + (b0 >> 1);
        const ulonglong2* Wp = (const ulonglong2*)Ws + s * 1024 + iq;
        #pragma unroll 8
        for (int j = 0; j < 128; j++) {
            ull zu = Zp[j * 8];
            float2 z = *(float2*)&zu;
            ulonglong2 wv = Wp[j * 8];
            ull pz;
            PACK2(pz, z.x); FFMA2(acc[0][0], pz, wv.x); FFMA2(acc[0][1], pz, wv.y);
            PACK2(pz, z.y); FFMA2(acc[1][0], pz, wv.x); FFMA2(acc[1][1], pz, wv.y);
        }
        int sg = s0 + s;
        #pragma unroll
        for (int bi = 0; bi < 2; bi++) {
            int b = b0 + bi;
            ulonglong2 o; o.x = acc[bi][0]; o.y = acc[bi][1];
            *(ulonglong2*)(g_T + (b * NB_S + sg) * NB_OUT + i0 + iq * 4) = o;
        }
    }
}

// ============================================================================
// K3 (unchanged from R15)
// ============================================================================
extern __shared__ float k3_sm[];
__global__ __launch_bounds__(512) void k3_link(
    const float* __restrict__ Lk, const float* __restrict__ rLk,
    float* __restrict__ out, const int* __restrict__ pL)
{
    const uint32_t sbase = (uint32_t)__cvta_generic_to_shared(k3_sm);

    const int tid = threadIdx.x;
    const int o0 = blockIdx.x * 32;
    const int b  = blockIdx.y;
    const int L  = pL[0];
    const int Lo = (L / 2) > 1 ? (L / 2) : 1;
    const int L2 = L * 2;

    const int w  = tid >> 5;
    const int l  = tid & 31;
    const int og = w & 3;
    const int q  = w >> 2;

    ull acc[8][2];
    #pragma unroll
    for (int a = 0; a < 8; a++) { acc[a][0] = 0ull; acc[a][1] = 0ull; }

    auto issue = [&](int c) {
        const int buf = c & 1;
        const uint32_t Ab = sbase + (buf ? 20480u : 0u) * 4u;
        const uint32_t Bb = sbase + (buf ? 24576u : 4096u) * 4u;
        const int kc = c * 128;
        #pragma unroll
        for (int t = 0; t < 2; t++) {
            int u = tid + t * 512;
            int k = u >> 3, part = u & 7;
            int kg = kc + k;
            bool ok = (kg < L2);
            int sg = (kg >> 1);
            const float* src = ((kg & 1) ? rLk : Lk) + (ok ? sg : 0) * NB_SO + o0 + part * 4;
            cp16(Ab + (uint32_t)(k * 32 + part * 4) * 4u, src, ok);
        }
        #pragma unroll
        for (int t = 0; t < 8; t++) {
            int u = tid + t * 512;
            int k = u >> 5, part = u & 31;
            int kg = kc + k;
            bool ok = (kg < L2);
            int sg = (kg >> 1);
            const float* src = ((kg & 1) ? g_R : g_T) + ((size_t)b * NB_S + (ok ? sg : 0)) * NB_OUT + part * 4;
            cp16(Bb + (uint32_t)(k * 128 + part * 4) * 4u, src, ok);
        }
        CP_COMMIT();
    };

    issue(0);

    for (int c = 0; c < 8; c++) {
        if (c < 7) {
            issue(c + 1);
            CP_WAIT(1);
        } else {
            CP_WAIT(0);
        }
        __syncthreads();

        const int buf = c & 1;
        const float* A = k3_sm + (buf ? 20480 : 0);
        const float* B = k3_sm + (buf ? 24576 : 4096);

        const float4* Af = (const float4*)A + (q * 32) * 8 + og * 2;
        const ulonglong2* B2 = (const ulonglong2*)B + (q * 32) * 32 + l;
        #pragma unroll 4
        for (int k = 0; k < 32; k++) {
            float4 a0 = Af[k * 8];
            float4 a1 = Af[k * 8 + 1];
            ulonglong2 bv = B2[k * 32];
            ull pa[8];
            PACK2(pa[0], a0.x); PACK2(pa[1], a0.y); PACK2(pa[2], a0.z); PACK2(pa[3], a0.w);
            PACK2(pa[4], a1.x); PACK2(pa[5], a1.y); PACK2(pa[6], a1.z); PACK2(pa[7], a1.w);
            #pragma unroll
            for (int oi = 0; oi < 8; oi++) {
                FFMA2(acc[oi][0], pa[oi], bv.x);
                FFMA2(acc[oi][1], pa[oi], bv.y);
            }
        }
        __syncthreads();
    }

    float* red = k3_sm + 4096;
    if (q > 0) {
        ulonglong2* st = (ulonglong2*)red + ((q - 1) * 4 + og) * 256;
        #pragma unroll
        for (int oi = 0; oi < 8; oi++) {
            ulonglong2 v; v.x = acc[oi][0]; v.y = acc[oi][1];
            st[oi * 32 + l] = v;
        }
    }
    __syncthreads();
    if (q == 0) {
        #pragma unroll
        for (int oi = 0; oi < 8; oi++) {
            #pragma unroll
            for (int qq = 0; qq < 3; qq++) {
                ulonglong2 v = ((const ulonglong2*)red)[(qq * 4 + og) * 256 + oi * 32 + l];
                ADD2(acc[oi][0], v.x);
                ADD2(acc[oi][1], v.y);
            }
            int o = o0 + og * 8 + oi;
            if (o < Lo) {
                ulonglong2 ov; ov.x = acc[oi][0]; ov.y = acc[oi][1];
                *(ulonglong2*)(out + (b * Lo + o) * NB_OUT + l * 4) = ov;
            }
        }
    }
}

// ============================================================================
extern "C" void kernel_launch(void* const* d_in, const int* in_sizes, int n_in,
                              void* d_out, int out_size)
{
    const float* x    = (const float*)d_in[0];
    const float* M    = (const float*)d_in[1];
    const float* P    = (const float*)d_in[2];
    const float* Lk   = (const float*)d_in[3];
    const float* lng  = (const float*)d_in[4];
    const float* lnb  = (const float*)d_in[5];
    const float* rW   = (const float*)d_in[6];
    const float* rLk  = (const float*)d_in[7];
    const int*   pL   = (const int*)d_in[9];
    float* out = (float*)d_out;

    cudaFuncSetAttribute(k1_proj_ln, cudaFuncAttributeMaxDynamicSharedMemorySize, 198144);
    cudaFuncSetAttribute(k2_mix,     cudaFuncAttributeMaxDynamicSharedMemorySize, 98304);
    cudaFuncSetAttribute(k3_link,    cudaFuncAttributeMaxDynamicSharedMemorySize, 163840);

    k0_transpose<<<dim3(8, 8), 256>>>(M, rW);
    k1_proj_ln<<<NB_S / 4, 512, 198144>>>(x, lng, lnb);
    k2_mix<<<dim3(NB_S / 4, NB_OUT / 32), 256, 98304>>>(P);
    k3_link<<<dim3(8, NB_B), 512, 163840>>>(Lk, rLk, out, pL);
}